// round 8
// baseline (speedup 1.0000x reference)
#include <cuda_runtime.h>
#include <cuda_bf16.h>
#include <mma.h>

using namespace nvcuda;

constexpr int B_   = 8;
constexpr int H_   = 8;
constexpr int S_   = 1024;
constexpr int DK_  = 64;
constexpr int EMB_ = 512;
constexpr int HD_  = 512;   // H*DK
constexpr int BH_  = 64;    // B*H
constexpr int SD_  = S_ * DK_;   // 65536
constexpr int SS_  = S_ * S_;    // 1048576
constexpr int TPAD = 1032;       // sT row stride (pad vs 1024)

// Scratch (device globals: allocation-free rule)
__device__ float gQ[BH_ * S_ * DK_];   // tf32-rounded, q pre-scaled by 1/8
__device__ float gK[BH_ * S_ * DK_];   // tf32-rounded
__device__ float gV[BH_ * S_ * DK_];   // tf32-rounded
__device__ float gO[BH_ * S_ * DK_];
// gS: fp32 score-bias before softmax; packed bf16(hi,lo) weights after softmax
__device__ float gS[(size_t)BH_ * S_ * S_];

__device__ __forceinline__ float tf32r(float x) { return wmma::__float_to_tf32(x); }

// ---------------------------------------------------------------------------
// Kernel 1: merged QKV projection, 3xbf16 split. Tile 128x64, k-chunk 32.
// ---------------------------------------------------------------------------
__global__ __launch_bounds__(256)
void proj_kernel(const float* __restrict__ Xq, const float* __restrict__ Xk,
                 const float* __restrict__ Xv,
                 const float* __restrict__ Wq, const float* __restrict__ Wk,
                 const float* __restrict__ Wv,
                 const float* __restrict__ bq, const float* __restrict__ bk,
                 const float* __restrict__ bv)
{
    __shared__ float sBias[16 * 72];
    __shared__ __nv_bfloat16 sAhi[128 * 40], sAlo[128 * 40];
    __shared__ __nv_bfloat16 sBhi[32 * 72],  sBlo[32 * 72];

    const int which = blockIdx.z;
    const float* X    = (which == 0) ? Xq : (which == 1) ? Xk : Xv;
    const float* W    = (which == 0) ? Wq : (which == 1) ? Wk : Wv;
    const float* bias = (which == 0) ? bq : (which == 1) ? bk : bv;
    float* outp       = (which == 0) ? gQ : (which == 1) ? gK : gV;
    const float scale = (which == 0) ? 0.125f : 1.0f;

    const int tid = threadIdx.x;
    const int wid = tid >> 5;
    const int warpRow = wid >> 1;
    const int warpCol = wid & 1;
    const int m0 = blockIdx.y * 128;
    const int n0 = blockIdx.x * 64;
    const int bb = m0 >> 10;
    const int sBase = m0 & 1023;
    const int h  = n0 >> 6;

    #pragma unroll
    for (int i = 0; i < 4; i++) {
        int idx = tid + i * 256;
        int r = idx >> 6, c = idx & 63;
        sBias[r * 72 + c] = bias[n0 + c];
    }
    __syncthreads();

    wmma::fragment<wmma::accumulator, 16, 16, 16, float> acc[2][2];
    #pragma unroll
    for (int mi = 0; mi < 2; mi++)
        #pragma unroll
        for (int ni = 0; ni < 2; ni++)
            wmma::load_matrix_sync(acc[mi][ni], sBias + warpCol * 32 + ni * 16,
                                   72, wmma::mem_row_major);

    for (int kt = 0; kt < 16; kt++) {
        const int k0 = kt * 32;
        #pragma unroll
        for (int i = 0; i < 4; i++) {
            int fi = tid + i * 256;
            int row = fi >> 3, c4 = (fi & 7) * 4;
            float4 v = *(const float4*)(X + (m0 + row) * EMB_ + k0 + c4);
            __nv_bfloat16 hx = __float2bfloat16(v.x), hy = __float2bfloat16(v.y);
            __nv_bfloat16 hz = __float2bfloat16(v.z), hw = __float2bfloat16(v.w);
            __nv_bfloat162 h01(hx, hy), h23(hz, hw);
            __nv_bfloat162 l01(__float2bfloat16(v.x - __bfloat162float(hx)),
                               __float2bfloat16(v.y - __bfloat162float(hy)));
            __nv_bfloat162 l23(__float2bfloat16(v.z - __bfloat162float(hz)),
                               __float2bfloat16(v.w - __bfloat162float(hw)));
            *(__nv_bfloat162*)&sAhi[row * 40 + c4]     = h01;
            *(__nv_bfloat162*)&sAhi[row * 40 + c4 + 2] = h23;
            *(__nv_bfloat162*)&sAlo[row * 40 + c4]     = l01;
            *(__nv_bfloat162*)&sAlo[row * 40 + c4 + 2] = l23;
        }
        #pragma unroll
        for (int i = 0; i < 2; i++) {
            int fi = tid + i * 256;
            int row = fi >> 4, c4 = (fi & 15) * 4;
            float4 v = *(const float4*)(W + (k0 + row) * HD_ + n0 + c4);
            __nv_bfloat16 hx = __float2bfloat16(v.x), hy = __float2bfloat16(v.y);
            __nv_bfloat16 hz = __float2bfloat16(v.z), hw = __float2bfloat16(v.w);
            __nv_bfloat162 h01(hx, hy), h23(hz, hw);
            __nv_bfloat162 l01(__float2bfloat16(v.x - __bfloat162float(hx)),
                               __float2bfloat16(v.y - __bfloat162float(hy)));
            __nv_bfloat162 l23(__float2bfloat16(v.z - __bfloat162float(hz)),
                               __float2bfloat16(v.w - __bfloat162float(hw)));
            *(__nv_bfloat162*)&sBhi[row * 72 + c4]     = h01;
            *(__nv_bfloat162*)&sBhi[row * 72 + c4 + 2] = h23;
            *(__nv_bfloat162*)&sBlo[row * 72 + c4]     = l01;
            *(__nv_bfloat162*)&sBlo[row * 72 + c4 + 2] = l23;
        }
        __syncthreads();
        #pragma unroll
        for (int kk = 0; kk < 2; kk++) {
            wmma::fragment<wmma::matrix_b, 16, 16, 16, __nv_bfloat16, wmma::row_major> bhf[2], blf[2];
            #pragma unroll
            for (int ni = 0; ni < 2; ni++) {
                wmma::load_matrix_sync(bhf[ni], sBhi + (kk * 16) * 72 + warpCol * 32 + ni * 16, 72);
                wmma::load_matrix_sync(blf[ni], sBlo + (kk * 16) * 72 + warpCol * 32 + ni * 16, 72);
            }
            #pragma unroll
            for (int mi = 0; mi < 2; mi++) {
                wmma::fragment<wmma::matrix_a, 16, 16, 16, __nv_bfloat16, wmma::row_major> ah, al;
                wmma::load_matrix_sync(ah, sAhi + (warpRow * 32 + mi * 16) * 40 + kk * 16, 40);
                wmma::load_matrix_sync(al, sAlo + (warpRow * 32 + mi * 16) * 40 + kk * 16, 40);
                #pragma unroll
                for (int ni = 0; ni < 2; ni++) {
                    wmma::mma_sync(acc[mi][ni], ah, bhf[ni], acc[mi][ni]);
                    wmma::mma_sync(acc[mi][ni], ah, blf[ni], acc[mi][ni]);
                    wmma::mma_sync(acc[mi][ni], al, bhf[ni], acc[mi][ni]);
                }
            }
        }
        __syncthreads();
    }

    float* obase = outp + ((bb * H_ + h) << 16);
    #pragma unroll
    for (int mi = 0; mi < 2; mi++)
        #pragma unroll
        for (int ni = 0; ni < 2; ni++) {
            #pragma unroll
            for (int e = 0; e < acc[mi][ni].num_elements; e++)
                acc[mi][ni].x[e] = tf32r(acc[mi][ni].x[e] * scale);
            wmma::store_matrix_sync(
                obase + (sBase + warpRow * 32 + mi * 16) * DK_ + warpCol * 32 + ni * 16,
                acc[mi][ni], DK_, wmma::mem_row_major);
        }
}

// ---------------------------------------------------------------------------
// Kernel 2: gS[bh,q,n] = gQ[bh,q,:]·Ek[q,n,:] + abias[b,q,n]. (fp32 phase)
// ---------------------------------------------------------------------------
__global__ __launch_bounds__(256, 4)
void edge_bias_kernel(const float* __restrict__ Ek, const float* __restrict__ abias)
{
    extern __shared__ float dsm[];
    float* sA    = dsm;                  // 64 x 68
    float* sEk   = dsm + 64 * 68;        // 64 x 68
    float* sBias = dsm + 2 * 64 * 68;    // 64 x 72

    const int tid = threadIdx.x;
    const int wid = tid >> 5;
    const int wr  = wid >> 2;
    const int wc  = wid & 3;
    const int q   = blockIdx.y;
    const int n0  = blockIdx.x * 64;
    const int rowA = tid >> 4;
    const int c4   = (tid & 15) * 4;

    #pragma unroll
    for (int i = 0; i < 4; i++) {
        int row = rowA + i * 16;
        *(float4*)(sA + row * 68 + c4) =
            *(const float4*)(gQ + (size_t)row * SD_ + q * DK_ + c4);
        *(float4*)(sEk + row * 68 + c4) =
            *(const float4*)(Ek + ((size_t)q * S_ + n0 + row) * DK_ + c4);
    }
    #pragma unroll
    for (int i = 0; i < 16; i++) {
        int idx = tid + i * 256;
        int r = idx >> 6, c = idx & 63;
        sBias[r * 72 + c] = abias[(size_t)(r >> 3) * SS_ + (size_t)q * S_ + n0 + c];
    }
    __syncthreads();

    wmma::fragment<wmma::accumulator, 16, 16, 8, float> acc[2];
    #pragma unroll
    for (int mi = 0; mi < 2; mi++)
        wmma::load_matrix_sync(acc[mi], sBias + (wr * 32 + mi * 16) * 72 + wc * 16,
                               72, wmma::mem_row_major);

    #pragma unroll
    for (int kk = 0; kk < 8; kk++) {
        wmma::fragment<wmma::matrix_b, 16, 16, 8, wmma::precision::tf32, wmma::col_major> b;
        wmma::load_matrix_sync(b, sEk + (wc * 16) * 68 + kk * 8, 68);
        #pragma unroll
        for (int mi = 0; mi < 2; mi++) {
            wmma::fragment<wmma::matrix_a, 16, 16, 8, wmma::precision::tf32, wmma::row_major> a;
            wmma::load_matrix_sync(a, sA + (wr * 32 + mi * 16) * 68 + kk * 8, 68);
            wmma::mma_sync(acc[mi], a, b, acc[mi]);
        }
    }

    #pragma unroll
    for (int mi = 0; mi < 2; mi++)
        wmma::store_matrix_sync(
            gS + (size_t)(wr * 32 + mi * 16) * SS_ + (size_t)q * S_ + n0 + wc * 16,
            acc[mi], SS_, wmma::mem_row_major);
}

// ---------------------------------------------------------------------------
// Kernel 3 (FUSED): scores -> softmax -> weights(packed bf16 hi/lo to gS)
//                   -> out = W @ V (gO).
// ---------------------------------------------------------------------------
__global__ __launch_bounds__(256, 1)
void fused_attn_kernel()
{
    extern __shared__ float dsm[];
    float* sQ  = dsm;                    // 32 x 72
    float* sKV = dsm + 32 * 72;          // 128 x 68
    float* sT  = dsm + 32 * 72 + 128 * 68;  // 32 x TPAD

    const int tid = threadIdx.x;
    const int wid = tid >> 5;
    const int lane = tid & 31;
    const int bh = blockIdx.y;
    const int q0 = blockIdx.x * 32;
    const int rowA = tid >> 4;
    const int c4   = (tid & 15) * 4;

    #pragma unroll
    for (int i = 0; i < 2; i++) {
        int fi = tid + i * 256;
        int row = fi >> 4, cc = (fi & 15) * 4;
        *(float4*)(sQ + row * 72 + cc) =
            *(const float4*)(gQ + bh * SD_ + (q0 + row) * DK_ + cc);
    }
    __syncthreads();

    // ---- Phase A: scores ----
    {
        const int wr = wid >> 2;
        const int wc = wid & 3;
        wmma::fragment<wmma::matrix_a, 16, 16, 8, wmma::precision::tf32, wmma::row_major> a[8];
        #pragma unroll
        for (int kk = 0; kk < 8; kk++)
            wmma::load_matrix_sync(a[kk], sQ + (wr * 16) * 72 + kk * 8, 72);

        const float* Kbase = gK + bh * SD_;
        const float* Sbase = gS + ((size_t)bh * S_ + q0 + wr * 16) * S_;

        float4 pK[8];
        #pragma unroll
        for (int i = 0; i < 8; i++)
            pK[i] = *(const float4*)(Kbase + (rowA + i * 16) * DK_ + c4);

        for (int nc = 0; nc < 8; nc++) {
            __syncthreads();
            #pragma unroll
            for (int i = 0; i < 8; i++)
                *(float4*)(sKV + (rowA + i * 16) * 68 + c4) = pK[i];
            __syncthreads();
            if (nc < 7) {
                const int n1 = (nc + 1) * 128;
                #pragma unroll
                for (int i = 0; i < 8; i++)
                    pK[i] = *(const float4*)(Kbase + (n1 + rowA + i * 16) * DK_ + c4);
            }
            #pragma unroll
            for (int ni = 0; ni < 2; ni++) {
                const int ncol = wc * 32 + ni * 16;
                wmma::fragment<wmma::accumulator, 16, 16, 8, float> acc;
                wmma::load_matrix_sync(acc, Sbase + nc * 128 + ncol, S_, wmma::mem_row_major);
                #pragma unroll
                for (int kk = 0; kk < 8; kk++) {
                    wmma::fragment<wmma::matrix_b, 16, 16, 8, wmma::precision::tf32, wmma::col_major> b;
                    wmma::load_matrix_sync(b, sKV + ncol * 68 + kk * 8, 68);
                    wmma::mma_sync(acc, a[kk], b, acc);
                }
                wmma::store_matrix_sync(sT + (wr * 16) * TPAD + nc * 128 + ncol,
                                        acc, TPAD, wmma::mem_row_major);
            }
        }
    }
    __syncthreads();

    // ---- Phase B: row softmax; sT gets tf32 weights, gS gets packed bf16 hi/lo ----
    #pragma unroll
    for (int rr = 0; rr < 4; rr++) {
        int r = wid * 4 + rr;
        float* row = sT + r * TPAD;
        float mx = -3.0e38f;
        for (int i = lane; i < 1024; i += 32) mx = fmaxf(mx, row[i]);
        #pragma unroll
        for (int o = 16; o; o >>= 1) mx = fmaxf(mx, __shfl_xor_sync(0xffffffffu, mx, o));
        float sum = 0.0f;
        for (int i = lane; i < 1024; i += 32) {
            float e = expf(row[i] - mx);
            row[i] = e;
            sum += e;
        }
        #pragma unroll
        for (int o = 16; o; o >>= 1) sum += __shfl_xor_sync(0xffffffffu, sum, o);
        float inv = 1.0f / sum;
        unsigned int* outw = (unsigned int*)(gS + ((size_t)bh * S_ + q0 + r) * S_);
        for (int i = lane; i < 1024; i += 32) {
            float w = row[i] * inv;
            __nv_bfloat16 hi = __float2bfloat16(w);
            __nv_bfloat16 lo = __float2bfloat16(w - __bfloat162float(hi));
            unsigned int phi = __bfloat16_as_ushort(hi);
            unsigned int plo = __bfloat16_as_ushort(lo);
            outw[i] = (plo << 16) | phi;
            row[i] = tf32r(w);
        }
    }

    // ---- Phase C: out = weights @ V ----
    {
        const int wr = wid >> 2;
        const int wc = wid & 3;
        wmma::fragment<wmma::accumulator, 16, 16, 8, float> c[2];
        wmma::fill_fragment(c[0], 0.0f);
        wmma::fill_fragment(c[1], 0.0f);
        const float* Vbase = gV + bh * SD_;
        const float* Tbase = sT + (wr * 16) * TPAD;

        float4 pV[4];
        #pragma unroll
        for (int i = 0; i < 4; i++)
            pV[i] = *(const float4*)(Vbase + (rowA + i * 16) * DK_ + c4);

        for (int kt = 0; kt < 16; kt++) {
            __syncthreads();
            #pragma unroll
            for (int i = 0; i < 4; i++)
                *(float4*)(sKV + (rowA + i * 16) * 68 + c4) = pV[i];
            __syncthreads();
            if (kt < 15) {
                const int k1 = (kt + 1) * 64;
                #pragma unroll
                for (int i = 0; i < 4; i++)
                    pV[i] = *(const float4*)(Vbase + (k1 + rowA + i * 16) * DK_ + c4);
            }
            #pragma unroll
            for (int kk = 0; kk < 8; kk++) {
                wmma::fragment<wmma::matrix_a, 16, 16, 8, wmma::precision::tf32, wmma::row_major> a;
                wmma::fragment<wmma::matrix_b, 16, 16, 8, wmma::precision::tf32, wmma::row_major> b;
                wmma::load_matrix_sync(a, Tbase + kt * 64 + kk * 8, TPAD);
                wmma::load_matrix_sync(b, sKV + (kk * 8) * 68 + wc * 16, 68);
                wmma::mma_sync(c[kk & 1], a, b, c[kk & 1]);
            }
        }
        #pragma unroll
        for (int e = 0; e < c[0].num_elements; e++) c[0].x[e] += c[1].x[e];
        wmma::store_matrix_sync(gO + bh * SD_ + (q0 + wr * 16) * DK_ + wc * 16,
                                c[0], DK_, wmma::mem_row_major);
    }
}

// ---------------------------------------------------------------------------
// Kernel 4: gO += weights[:,q,:] @ Ev[q].  bf16 2x2-split (minus lo*lo).
// A = packed (hi,lo) weights from gS; B = Ev split at staging. LDSM path.
// ---------------------------------------------------------------------------
__global__ __launch_bounds__(256, 4)
void edgev_kernel(const float* __restrict__ Ev)
{
    __shared__ __nv_bfloat16 sAhi[64 * 72], sAlo[64 * 72];
    __shared__ __nv_bfloat16 sBhi[64 * 72], sBlo[64 * 72];

    const int tid = threadIdx.x;
    const int wid = tid >> 5;
    const int warpRow = wid >> 1;   // 0..3 -> 16 bh rows
    const int warpCol = wid & 1;    // 0..1 -> 32 cols
    const int q = blockIdx.x;
    const int rowA = tid >> 4;      // 0..15
    const int c4   = (tid & 15) * 4;

    wmma::fragment<wmma::accumulator, 16, 16, 16, float> acc[2];
    #pragma unroll
    for (int j = 0; j < 2; j++)
        wmma::load_matrix_sync(acc[j],
            gO + (size_t)(warpRow * 16) * SD_ + q * DK_ + warpCol * 32 + j * 16,
            SD_, wmma::mem_row_major);

    uint4  pA[4];
    float4 pB[4];
    #pragma unroll
    for (int i = 0; i < 4; i++) {
        int row = rowA + i * 16;
        pA[i] = *(const uint4*)(gS + (size_t)row * SS_ + (size_t)q * S_ + c4);
        pB[i] = *(const float4*)(Ev + ((size_t)q * S_ + row) * DK_ + c4);
    }

    for (int kt = 0; kt < 16; kt++) {
        __syncthreads();
        #pragma unroll
        for (int i = 0; i < 4; i++) {
            int row = rowA + i * 16;
            // unpack packed (hi,lo): low 16 bits = hi, high 16 = lo
            uint4 pa = pA[i];
            *(unsigned int*)&sAhi[row * 72 + c4]     = __byte_perm(pa.x, pa.y, 0x5410);
            *(unsigned int*)&sAhi[row * 72 + c4 + 2] = __byte_perm(pa.z, pa.w, 0x5410);
            *(unsigned int*)&sAlo[row * 72 + c4]     = __byte_perm(pa.x, pa.y, 0x7632);
            *(unsigned int*)&sAlo[row * 72 + c4 + 2] = __byte_perm(pa.z, pa.w, 0x7632);
            float4 v = pB[i];
            __nv_bfloat16 hx = __float2bfloat16(v.x), hy = __float2bfloat16(v.y);
            __nv_bfloat16 hz = __float2bfloat16(v.z), hw = __float2bfloat16(v.w);
            *(__nv_bfloat162*)&sBhi[row * 72 + c4]     = __nv_bfloat162(hx, hy);
            *(__nv_bfloat162*)&sBhi[row * 72 + c4 + 2] = __nv_bfloat162(hz, hw);
            *(__nv_bfloat162*)&sBlo[row * 72 + c4] =
                __nv_bfloat162(__float2bfloat16(v.x - __bfloat162float(hx)),
                               __float2bfloat16(v.y - __bfloat162float(hy)));
            *(__nv_bfloat162*)&sBlo[row * 72 + c4 + 2] =
                __nv_bfloat162(__float2bfloat16(v.z - __bfloat162float(hz)),
                               __float2bfloat16(v.w - __bfloat162float(hw)));
        }
        __syncthreads();
        if (kt < 15) {
            const int k1 = (kt + 1) * 64;
            #pragma unroll
            for (int i = 0; i < 4; i++) {
                int row = rowA + i * 16;
                pA[i] = *(const uint4*)(gS + (size_t)row * SS_ + (size_t)q * S_ + k1 + c4);
                pB[i] = *(const float4*)(Ev + ((size_t)q * S_ + k1 + row) * DK_ + c4);
            }
        }
        #pragma unroll
        for (int kk = 0; kk < 4; kk++) {
            wmma::fragment<wmma::matrix_a, 16, 16, 16, __nv_bfloat16, wmma::row_major> ah, al;
            wmma::load_matrix_sync(ah, sAhi + (warpRow * 16) * 72 + kk * 16, 72);
            wmma::load_matrix_sync(al, sAlo + (warpRow * 16) * 72 + kk * 16, 72);
            #pragma unroll
            for (int j = 0; j < 2; j++) {
                wmma::fragment<wmma::matrix_b, 16, 16, 16, __nv_bfloat16, wmma::row_major> bh, bl;
                wmma::load_matrix_sync(bh, sBhi + (kk * 16) * 72 + warpCol * 32 + j * 16, 72);
                wmma::load_matrix_sync(bl, sBlo + (kk * 16) * 72 + warpCol * 32 + j * 16, 72);
                wmma::mma_sync(acc[j], ah, bh, acc[j]);
                wmma::mma_sync(acc[j], ah, bl, acc[j]);
                wmma::mma_sync(acc[j], al, bh, acc[j]);
            }
        }
    }

    #pragma unroll
    for (int j = 0; j < 2; j++)
        wmma::store_matrix_sync(
            gO + (size_t)(warpRow * 16) * SD_ + q * DK_ + warpCol * 32 + j * 16,
            acc[j], SD_, wmma::mem_row_major);
}

// ---------------------------------------------------------------------------
// Kernel 5: out = concat_heads(gO) @ Wp + bp. 3xbf16 split, tile 128x64.
// ---------------------------------------------------------------------------
__global__ __launch_bounds__(256)
void final_kernel(const float* __restrict__ Wp, const float* __restrict__ bp,
                  float* __restrict__ out)
{
    __shared__ float sBias[16 * 72];
    __shared__ __nv_bfloat16 sAhi[128 * 40], sAlo[128 * 40];
    __shared__ __nv_bfloat16 sBhi[32 * 72],  sBlo[32 * 72];

    const int tid = threadIdx.x;
    const int wid = tid >> 5;
    const int warpRow = wid >> 1;
    const int warpCol = wid & 1;
    const int m0 = blockIdx.y * 128;
    const int n0 = blockIdx.x * 64;
    const int bb = m0 >> 10;
    const int sBase = m0 & 1023;

    #pragma unroll
    for (int i = 0; i < 4; i++) {
        int idx = tid + i * 256;
        int r = idx >> 6, c = idx & 63;
        sBias[r * 72 + c] = bp[n0 + c];
    }
    __syncthreads();

    wmma::fragment<wmma::accumulator, 16, 16, 16, float> acc[2][2];
    #pragma unroll
    for (int mi = 0; mi < 2; mi++)
        #pragma unroll
        for (int ni = 0; ni < 2; ni++)
            wmma::load_matrix_sync(acc[mi][ni], sBias + warpCol * 32 + ni * 16,
                                   72, wmma::mem_row_major);

    for (int kt = 0; kt < 16; kt++) {
        const int k0 = kt * 32;
        const int h = k0 >> 6, d0 = k0 & 63;
        const float* Abase = gO + ((bb * H_ + h) << 16) + d0;
        #pragma unroll
        for (int i = 0; i < 4; i++) {
            int fi = tid + i * 256;
            int row = fi >> 3, c4 = (fi & 7) * 4;
            float4 v = *(const float4*)(Abase + (sBase + row) * DK_ + c4);
            __nv_bfloat16 hx = __float2bfloat16(v.x), hy = __float2bfloat16(v.y);
            __nv_bfloat16 hz = __float2bfloat16(v.z), hw = __float2bfloat16(v.w);
            __nv_bfloat162 h01(hx, hy), h23(hz, hw);
            __nv_bfloat162 l01(__float2bfloat16(v.x - __bfloat162float(hx)),
                               __float2bfloat16(v.y - __bfloat162float(hy)));
            __nv_bfloat162 l23(__float2bfloat16(v.z - __bfloat162float(hz)),
                               __float2bfloat16(v.w - __bfloat162float(hw)));
            *(__nv_bfloat162*)&sAhi[row * 40 + c4]     = h01;
            *(__nv_bfloat162*)&sAhi[row * 40 + c4 + 2] = h23;
            *(__nv_bfloat162*)&sAlo[row * 40 + c4]     = l01;
            *(__nv_bfloat162*)&sAlo[row * 40 + c4 + 2] = l23;
        }
        #pragma unroll
        for (int i = 0; i < 2; i++) {
            int fi = tid + i * 256;
            int row = fi >> 4, c4 = (fi & 15) * 4;
            float4 v = *(const float4*)(Wp + (k0 + row) * HD_ + n0 + c4);
            __nv_bfloat16 hx = __float2bfloat16(v.x), hy = __float2bfloat16(v.y);
            __nv_bfloat16 hz = __float2bfloat16(v.z), hw = __float2bfloat16(v.w);
            __nv_bfloat162 h01(hx, hy), h23(hz, hw);
            __nv_bfloat162 l01(__float2bfloat16(v.x - __bfloat162float(hx)),
                               __float2bfloat16(v.y - __bfloat162float(hy)));
            __nv_bfloat162 l23(__float2bfloat16(v.z - __bfloat162float(hz)),
                               __float2bfloat16(v.w - __bfloat162float(hw)));
            *(__nv_bfloat162*)&sBhi[row * 72 + c4]     = h01;
            *(__nv_bfloat162*)&sBhi[row * 72 + c4 + 2] = h23;
            *(__nv_bfloat162*)&sBlo[row * 72 + c4]     = l01;
            *(__nv_bfloat162*)&sBlo[row * 72 + c4 + 2] = l23;
        }
        __syncthreads();
        #pragma unroll
        for (int kk = 0; kk < 2; kk++) {
            wmma::fragment<wmma::matrix_b, 16, 16, 16, __nv_bfloat16, wmma::row_major> bhf[2], blf[2];
            #pragma unroll
            for (int ni = 0; ni < 2; ni++) {
                wmma::load_matrix_sync(bhf[ni], sBhi + (kk * 16) * 72 + warpCol * 32 + ni * 16, 72);
                wmma::load_matrix_sync(blf[ni], sBlo + (kk * 16) * 72 + warpCol * 32 + ni * 16, 72);
            }
            #pragma unroll
            for (int mi = 0; mi < 2; mi++) {
                wmma::fragment<wmma::matrix_a, 16, 16, 16, __nv_bfloat16, wmma::row_major> ah, al;
                wmma::load_matrix_sync(ah, sAhi + (warpRow * 32 + mi * 16) * 40 + kk * 16, 40);
                wmma::load_matrix_sync(al, sAlo + (warpRow * 32 + mi * 16) * 40 + kk * 16, 40);
                #pragma unroll
                for (int ni = 0; ni < 2; ni++) {
                    wmma::mma_sync(acc[mi][ni], ah, bhf[ni], acc[mi][ni]);
                    wmma::mma_sync(acc[mi][ni], ah, blf[ni], acc[mi][ni]);
                    wmma::mma_sync(acc[mi][ni], al, bhf[ni], acc[mi][ni]);
                }
            }
        }
        __syncthreads();
    }

    #pragma unroll
    for (int mi = 0; mi < 2; mi++)
        #pragma unroll
        for (int ni = 0; ni < 2; ni++)
            wmma::store_matrix_sync(
                out + (m0 + warpRow * 32 + mi * 16) * HD_ + n0 + warpCol * 32 + ni * 16,
                acc[mi][ni], HD_, wmma::mem_row_major);
}

// ---------------------------------------------------------------------------
extern "C" void kernel_launch(void* const* d_in, const int* in_sizes, int n_in,
                              void* d_out, int out_size)
{
    const float* queries = (const float*)d_in[0];
    const float* keys    = (const float*)d_in[1];
    const float* values  = (const float*)d_in[2];
    const float* Ek      = (const float*)d_in[3];
    const float* Ev      = (const float*)d_in[4];
    const float* abias   = (const float*)d_in[5];
    const float* Wq = (const float*)d_in[6];
    const float* bq = (const float*)d_in[7];
    const float* Wk = (const float*)d_in[8];
    const float* bk = (const float*)d_in[9];
    const float* Wv = (const float*)d_in[10];
    const float* bv = (const float*)d_in[11];
    const float* Wp = (const float*)d_in[12];
    const float* bp = (const float*)d_in[13];
    float* out = (float*)d_out;

    const int SMEM_EB = (2 * 64 * 68 + 64 * 72) * (int)sizeof(float);           // 53248
    const int SMEM_FA = (32 * 72 + 128 * 68 + 32 * TPAD) * (int)sizeof(float);  // 176128
    cudaFuncSetAttribute(edge_bias_kernel, cudaFuncAttributeMaxDynamicSharedMemorySize, SMEM_EB);
    cudaFuncSetAttribute(fused_attn_kernel, cudaFuncAttributeMaxDynamicSharedMemorySize, SMEM_FA);

    dim3 blk(256);
    proj_kernel<<<dim3(8, 64, 3), blk>>>(queries, keys, values, Wq, Wk, Wv, bq, bk, bv);
    edge_bias_kernel<<<dim3(16, 1024), blk, SMEM_EB>>>(Ek, abias);
    fused_attn_kernel<<<dim3(32, 64), blk, SMEM_FA>>>();
    edgev_kernel<<<1024, blk>>>(Ev);
    final_kernel<<<dim3(8, 64), blk>>>(Wp, bp, out);
}

// round 9
// speedup vs baseline: 1.0471x; 1.0471x over previous
#include <cuda_runtime.h>
#include <cuda_bf16.h>
#include <cuda_fp16.h>
#include <mma.h>

using namespace nvcuda;

constexpr int B_   = 8;
constexpr int H_   = 8;
constexpr int S_   = 1024;
constexpr int DK_  = 64;
constexpr int EMB_ = 512;
constexpr int HD_  = 512;   // H*DK
constexpr int BH_  = 64;    // B*H
constexpr int SD_  = S_ * DK_;   // 65536
constexpr int SS_  = S_ * S_;    // 1048576
constexpr int TPAD = 1032;       // sT row stride (pad vs 1024)

// Scratch (device globals: allocation-free rule)
__device__ float gQ[BH_ * S_ * DK_];   // tf32-rounded, q pre-scaled by 1/8
__device__ float gK[BH_ * S_ * DK_];   // tf32-rounded
__device__ float gV[BH_ * S_ * DK_];   // tf32-rounded
__device__ float gO[BH_ * S_ * DK_];
// gS: fp32 score-bias before softmax; fp16 weights (first 2KB of each row) after
__device__ float gS[(size_t)BH_ * S_ * S_];

__device__ __forceinline__ float tf32r(float x) { return wmma::__float_to_tf32(x); }

// ---------------------------------------------------------------------------
// Kernel 1: merged QKV projection, 3xbf16 split. Tile 128x64, k-chunk 32.
// ---------------------------------------------------------------------------
__global__ __launch_bounds__(256)
void proj_kernel(const float* __restrict__ Xq, const float* __restrict__ Xk,
                 const float* __restrict__ Xv,
                 const float* __restrict__ Wq, const float* __restrict__ Wk,
                 const float* __restrict__ Wv,
                 const float* __restrict__ bq, const float* __restrict__ bk,
                 const float* __restrict__ bv)
{
    __shared__ float sBias[16 * 72];
    __shared__ __nv_bfloat16 sAhi[128 * 40], sAlo[128 * 40];
    __shared__ __nv_bfloat16 sBhi[32 * 72],  sBlo[32 * 72];

    const int which = blockIdx.z;
    const float* X    = (which == 0) ? Xq : (which == 1) ? Xk : Xv;
    const float* W    = (which == 0) ? Wq : (which == 1) ? Wk : Wv;
    const float* bias = (which == 0) ? bq : (which == 1) ? bk : bv;
    float* outp       = (which == 0) ? gQ : (which == 1) ? gK : gV;
    const float scale = (which == 0) ? 0.125f : 1.0f;

    const int tid = threadIdx.x;
    const int wid = tid >> 5;
    const int warpRow = wid >> 1;
    const int warpCol = wid & 1;
    const int m0 = blockIdx.y * 128;
    const int n0 = blockIdx.x * 64;
    const int bb = m0 >> 10;
    const int sBase = m0 & 1023;
    const int h  = n0 >> 6;

    #pragma unroll
    for (int i = 0; i < 4; i++) {
        int idx = tid + i * 256;
        int r = idx >> 6, c = idx & 63;
        sBias[r * 72 + c] = bias[n0 + c];
    }
    __syncthreads();

    wmma::fragment<wmma::accumulator, 16, 16, 16, float> acc[2][2];
    #pragma unroll
    for (int mi = 0; mi < 2; mi++)
        #pragma unroll
        for (int ni = 0; ni < 2; ni++)
            wmma::load_matrix_sync(acc[mi][ni], sBias + warpCol * 32 + ni * 16,
                                   72, wmma::mem_row_major);

    for (int kt = 0; kt < 16; kt++) {
        const int k0 = kt * 32;
        #pragma unroll
        for (int i = 0; i < 4; i++) {
            int fi = tid + i * 256;
            int row = fi >> 3, c4 = (fi & 7) * 4;
            float4 v = *(const float4*)(X + (m0 + row) * EMB_ + k0 + c4);
            __nv_bfloat16 hx = __float2bfloat16(v.x), hy = __float2bfloat16(v.y);
            __nv_bfloat16 hz = __float2bfloat16(v.z), hw = __float2bfloat16(v.w);
            __nv_bfloat162 h01(hx, hy), h23(hz, hw);
            __nv_bfloat162 l01(__float2bfloat16(v.x - __bfloat162float(hx)),
                               __float2bfloat16(v.y - __bfloat162float(hy)));
            __nv_bfloat162 l23(__float2bfloat16(v.z - __bfloat162float(hz)),
                               __float2bfloat16(v.w - __bfloat162float(hw)));
            *(__nv_bfloat162*)&sAhi[row * 40 + c4]     = h01;
            *(__nv_bfloat162*)&sAhi[row * 40 + c4 + 2] = h23;
            *(__nv_bfloat162*)&sAlo[row * 40 + c4]     = l01;
            *(__nv_bfloat162*)&sAlo[row * 40 + c4 + 2] = l23;
        }
        #pragma unroll
        for (int i = 0; i < 2; i++) {
            int fi = tid + i * 256;
            int row = fi >> 4, c4 = (fi & 15) * 4;
            float4 v = *(const float4*)(W + (k0 + row) * HD_ + n0 + c4);
            __nv_bfloat16 hx = __float2bfloat16(v.x), hy = __float2bfloat16(v.y);
            __nv_bfloat16 hz = __float2bfloat16(v.z), hw = __float2bfloat16(v.w);
            __nv_bfloat162 h01(hx, hy), h23(hz, hw);
            __nv_bfloat162 l01(__float2bfloat16(v.x - __bfloat162float(hx)),
                               __float2bfloat16(v.y - __bfloat162float(hy)));
            __nv_bfloat162 l23(__float2bfloat16(v.z - __bfloat162float(hz)),
                               __float2bfloat16(v.w - __bfloat162float(hw)));
            *(__nv_bfloat162*)&sBhi[row * 72 + c4]     = h01;
            *(__nv_bfloat162*)&sBhi[row * 72 + c4 + 2] = h23;
            *(__nv_bfloat162*)&sBlo[row * 72 + c4]     = l01;
            *(__nv_bfloat162*)&sBlo[row * 72 + c4 + 2] = l23;
        }
        __syncthreads();
        #pragma unroll
        for (int kk = 0; kk < 2; kk++) {
            wmma::fragment<wmma::matrix_b, 16, 16, 16, __nv_bfloat16, wmma::row_major> bhf[2], blf[2];
            #pragma unroll
            for (int ni = 0; ni < 2; ni++) {
                wmma::load_matrix_sync(bhf[ni], sBhi + (kk * 16) * 72 + warpCol * 32 + ni * 16, 72);
                wmma::load_matrix_sync(blf[ni], sBlo + (kk * 16) * 72 + warpCol * 32 + ni * 16, 72);
            }
            #pragma unroll
            for (int mi = 0; mi < 2; mi++) {
                wmma::fragment<wmma::matrix_a, 16, 16, 16, __nv_bfloat16, wmma::row_major> ah, al;
                wmma::load_matrix_sync(ah, sAhi + (warpRow * 32 + mi * 16) * 40 + kk * 16, 40);
                wmma::load_matrix_sync(al, sAlo + (warpRow * 32 + mi * 16) * 40 + kk * 16, 40);
                #pragma unroll
                for (int ni = 0; ni < 2; ni++) {
                    wmma::mma_sync(acc[mi][ni], ah, bhf[ni], acc[mi][ni]);
                    wmma::mma_sync(acc[mi][ni], ah, blf[ni], acc[mi][ni]);
                    wmma::mma_sync(acc[mi][ni], al, bhf[ni], acc[mi][ni]);
                }
            }
        }
        __syncthreads();
    }

    float* obase = outp + ((bb * H_ + h) << 16);
    #pragma unroll
    for (int mi = 0; mi < 2; mi++)
        #pragma unroll
        for (int ni = 0; ni < 2; ni++) {
            #pragma unroll
            for (int e = 0; e < acc[mi][ni].num_elements; e++)
                acc[mi][ni].x[e] = tf32r(acc[mi][ni].x[e] * scale);
            wmma::store_matrix_sync(
                obase + (sBase + warpRow * 32 + mi * 16) * DK_ + warpCol * 32 + ni * 16,
                acc[mi][ni], DK_, wmma::mem_row_major);
        }
}

// ---------------------------------------------------------------------------
// Kernel 2: gS[bh,q,n] = gQ[bh,q,:]·Ek[q,n,:] + abias[b,q,n]. (fp32 phase)
// ---------------------------------------------------------------------------
__global__ __launch_bounds__(256, 4)
void edge_bias_kernel(const float* __restrict__ Ek, const float* __restrict__ abias)
{
    extern __shared__ float dsm[];
    float* sA    = dsm;                  // 64 x 68
    float* sEk   = dsm + 64 * 68;        // 64 x 68
    float* sBias = dsm + 2 * 64 * 68;    // 64 x 72

    const int tid = threadIdx.x;
    const int wid = tid >> 5;
    const int wr  = wid >> 2;
    const int wc  = wid & 3;
    const int q   = blockIdx.y;
    const int n0  = blockIdx.x * 64;
    const int rowA = tid >> 4;
    const int c4   = (tid & 15) * 4;

    #pragma unroll
    for (int i = 0; i < 4; i++) {
        int row = rowA + i * 16;
        *(float4*)(sA + row * 68 + c4) =
            *(const float4*)(gQ + (size_t)row * SD_ + q * DK_ + c4);
        *(float4*)(sEk + row * 68 + c4) =
            *(const float4*)(Ek + ((size_t)q * S_ + n0 + row) * DK_ + c4);
    }
    #pragma unroll
    for (int i = 0; i < 16; i++) {
        int idx = tid + i * 256;
        int r = idx >> 6, c = idx & 63;
        sBias[r * 72 + c] = abias[(size_t)(r >> 3) * SS_ + (size_t)q * S_ + n0 + c];
    }
    __syncthreads();

    wmma::fragment<wmma::accumulator, 16, 16, 8, float> acc[2];
    #pragma unroll
    for (int mi = 0; mi < 2; mi++)
        wmma::load_matrix_sync(acc[mi], sBias + (wr * 32 + mi * 16) * 72 + wc * 16,
                               72, wmma::mem_row_major);

    #pragma unroll
    for (int kk = 0; kk < 8; kk++) {
        wmma::fragment<wmma::matrix_b, 16, 16, 8, wmma::precision::tf32, wmma::col_major> b;
        wmma::load_matrix_sync(b, sEk + (wc * 16) * 68 + kk * 8, 68);
        #pragma unroll
        for (int mi = 0; mi < 2; mi++) {
            wmma::fragment<wmma::matrix_a, 16, 16, 8, wmma::precision::tf32, wmma::row_major> a;
            wmma::load_matrix_sync(a, sA + (wr * 32 + mi * 16) * 68 + kk * 8, 68);
            wmma::mma_sync(acc[mi], a, b, acc[mi]);
        }
    }

    #pragma unroll
    for (int mi = 0; mi < 2; mi++)
        wmma::store_matrix_sync(
            gS + (size_t)(wr * 32 + mi * 16) * SS_ + (size_t)q * S_ + n0 + wc * 16,
            acc[mi], SS_, wmma::mem_row_major);
}

// ---------------------------------------------------------------------------
// Kernel 3 (FUSED): scores (acc=0) -> +bias (coalesced) -> softmax
//                   -> fp16 weights to gS, tf32 weights to sT -> W @ V (gO).
// ---------------------------------------------------------------------------
__global__ __launch_bounds__(256, 1)
void fused_attn_kernel()
{
    extern __shared__ float dsm[];
    float* sQ  = dsm;                    // 32 x 72
    float* sKV = dsm + 32 * 72;          // 128 x 68
    float* sT  = dsm + 32 * 72 + 128 * 68;  // 32 x TPAD

    const int tid = threadIdx.x;
    const int wid = tid >> 5;
    const int lane = tid & 31;
    const int bh = blockIdx.y;
    const int q0 = blockIdx.x * 32;
    const int rowA = tid >> 4;
    const int c4   = (tid & 15) * 4;

    #pragma unroll
    for (int i = 0; i < 2; i++) {
        int fi = tid + i * 256;
        int row = fi >> 4, cc = (fi & 15) * 4;
        *(float4*)(sQ + row * 72 + cc) =
            *(const float4*)(gQ + bh * SD_ + (q0 + row) * DK_ + cc);
    }
    __syncthreads();

    // ---- Phase A: raw scores (no bias) ----
    {
        const int wr = wid >> 2;
        const int wc = wid & 3;
        wmma::fragment<wmma::matrix_a, 16, 16, 8, wmma::precision::tf32, wmma::row_major> a[8];
        #pragma unroll
        for (int kk = 0; kk < 8; kk++)
            wmma::load_matrix_sync(a[kk], sQ + (wr * 16) * 72 + kk * 8, 72);

        const float* Kbase = gK + bh * SD_;

        float4 pK[8];
        #pragma unroll
        for (int i = 0; i < 8; i++)
            pK[i] = *(const float4*)(Kbase + (rowA + i * 16) * DK_ + c4);

        for (int nc = 0; nc < 8; nc++) {
            __syncthreads();
            #pragma unroll
            for (int i = 0; i < 8; i++)
                *(float4*)(sKV + (rowA + i * 16) * 68 + c4) = pK[i];
            __syncthreads();
            if (nc < 7) {
                const int n1 = (nc + 1) * 128;
                #pragma unroll
                for (int i = 0; i < 8; i++)
                    pK[i] = *(const float4*)(Kbase + (n1 + rowA + i * 16) * DK_ + c4);
            }
            #pragma unroll
            for (int ni = 0; ni < 2; ni++) {
                const int ncol = wc * 32 + ni * 16;
                wmma::fragment<wmma::accumulator, 16, 16, 8, float> acc;
                wmma::fill_fragment(acc, 0.0f);
                #pragma unroll
                for (int kk = 0; kk < 8; kk++) {
                    wmma::fragment<wmma::matrix_b, 16, 16, 8, wmma::precision::tf32, wmma::col_major> b;
                    wmma::load_matrix_sync(b, sKV + ncol * 68 + kk * 8, 68);
                    wmma::mma_sync(acc, a[kk], b, acc);
                }
                wmma::store_matrix_sync(sT + (wr * 16) * TPAD + nc * 128 + ncol,
                                        acc, TPAD, wmma::mem_row_major);
            }
        }
    }
    __syncthreads();

    // ---- Phase B: add bias (coalesced), softmax; fp16 weights -> gS, tf32 -> sT ----
    #pragma unroll
    for (int rr = 0; rr < 4; rr++) {
        int r = wid * 4 + rr;
        float* row = sT + r * TPAD;
        float* grow = gS + ((size_t)bh * S_ + q0 + r) * S_;
        float mx = -3.0e38f;
        for (int i = lane; i < 1024; i += 32) {
            float v = row[i] + grow[i];
            row[i] = v;
            mx = fmaxf(mx, v);
        }
        #pragma unroll
        for (int o = 16; o; o >>= 1) mx = fmaxf(mx, __shfl_xor_sync(0xffffffffu, mx, o));
        float sum = 0.0f;
        for (int i = lane; i < 1024; i += 32) {
            float e = expf(row[i] - mx);
            row[i] = e;
            sum += e;
        }
        #pragma unroll
        for (int o = 16; o; o >>= 1) sum += __shfl_xor_sync(0xffffffffu, sum, o);
        float inv = 1.0f / sum;
        __half* outw = (__half*)grow;
        for (int i = lane; i < 1024; i += 32) {
            float w = row[i] * inv;
            outw[i] = __float2half_rn(w);
            row[i] = tf32r(w);
        }
    }

    // ---- Phase C: out = weights @ V ----
    {
        const int wr = wid >> 2;
        const int wc = wid & 3;
        wmma::fragment<wmma::accumulator, 16, 16, 8, float> c[2];
        wmma::fill_fragment(c[0], 0.0f);
        wmma::fill_fragment(c[1], 0.0f);
        const float* Vbase = gV + bh * SD_;
        const float* Tbase = sT + (wr * 16) * TPAD;

        float4 pV[4];
        #pragma unroll
        for (int i = 0; i < 4; i++)
            pV[i] = *(const float4*)(Vbase + (rowA + i * 16) * DK_ + c4);

        for (int kt = 0; kt < 16; kt++) {
            __syncthreads();
            #pragma unroll
            for (int i = 0; i < 4; i++)
                *(float4*)(sKV + (rowA + i * 16) * 68 + c4) = pV[i];
            __syncthreads();
            if (kt < 15) {
                const int k1 = (kt + 1) * 64;
                #pragma unroll
                for (int i = 0; i < 4; i++)
                    pV[i] = *(const float4*)(Vbase + (k1 + rowA + i * 16) * DK_ + c4);
            }
            #pragma unroll
            for (int kk = 0; kk < 8; kk++) {
                wmma::fragment<wmma::matrix_a, 16, 16, 8, wmma::precision::tf32, wmma::row_major> a;
                wmma::fragment<wmma::matrix_b, 16, 16, 8, wmma::precision::tf32, wmma::row_major> b;
                wmma::load_matrix_sync(a, Tbase + kt * 64 + kk * 8, TPAD);
                wmma::load_matrix_sync(b, sKV + (kk * 8) * 68 + wc * 16, 68);
                wmma::mma_sync(c[kk & 1], a, b, c[kk & 1]);
            }
        }
        #pragma unroll
        for (int e = 0; e < c[0].num_elements; e++) c[0].x[e] += c[1].x[e];
        wmma::store_matrix_sync(gO + bh * SD_ + (q0 + wr * 16) * DK_ + wc * 16,
                                c[0], DK_, wmma::mem_row_major);
    }
}

// ---------------------------------------------------------------------------
// Kernel 4: gO += weights[:,q,:] @ Ev[q].  Pure fp16 MMA (weights fp16 in gS,
// Ev converted at staging). Halved bytes through L1/DRAM vs fp32 path.
// ---------------------------------------------------------------------------
__global__ __launch_bounds__(256, 4)
void edgev_kernel(const float* __restrict__ Ev)
{
    __shared__ __half sA[64 * 72];
    __shared__ __half sB[64 * 72];

    const int tid = threadIdx.x;
    const int wid = tid >> 5;
    const int warpRow = wid >> 1;   // 0..3 -> 16 bh rows
    const int warpCol = wid & 1;    // 0..1 -> 32 cols
    const int q = blockIdx.x;
    const int rowA = tid >> 4;      // 0..15
    const int c4   = (tid & 15) * 4;

    wmma::fragment<wmma::accumulator, 16, 16, 16, float> acc[2];
    #pragma unroll
    for (int j = 0; j < 2; j++)
        wmma::load_matrix_sync(acc[j],
            gO + (size_t)(warpRow * 16) * SD_ + q * DK_ + warpCol * 32 + j * 16,
            SD_, wmma::mem_row_major);

    uint2  pA[4];
    float4 pB[4];
    #pragma unroll
    for (int i = 0; i < 4; i++) {
        int row = rowA + i * 16;
        pA[i] = *(const uint2*)((const __half*)(gS + (size_t)row * SS_ + (size_t)q * S_) + c4);
        pB[i] = *(const float4*)(Ev + ((size_t)q * S_ + row) * DK_ + c4);
    }

    for (int kt = 0; kt < 16; kt++) {
        __syncthreads();
        #pragma unroll
        for (int i = 0; i < 4; i++) {
            int row = rowA + i * 16;
            *(uint2*)&sA[row * 72 + c4] = pA[i];
            float4 v = pB[i];
            *(__half2*)&sB[row * 72 + c4]     = __floats2half2_rn(v.x, v.y);
            *(__half2*)&sB[row * 72 + c4 + 2] = __floats2half2_rn(v.z, v.w);
        }
        __syncthreads();
        if (kt < 15) {
            const int k1 = (kt + 1) * 64;
            #pragma unroll
            for (int i = 0; i < 4; i++) {
                int row = rowA + i * 16;
                pA[i] = *(const uint2*)((const __half*)(gS + (size_t)row * SS_ + (size_t)q * S_) + k1 + c4);
                pB[i] = *(const float4*)(Ev + ((size_t)q * S_ + k1 + row) * DK_ + c4);
            }
        }
        #pragma unroll
        for (int kk = 0; kk < 4; kk++) {
            wmma::fragment<wmma::matrix_a, 16, 16, 16, __half, wmma::row_major> a;
            wmma::load_matrix_sync(a, sA + (warpRow * 16) * 72 + kk * 16, 72);
            #pragma unroll
            for (int j = 0; j < 2; j++) {
                wmma::fragment<wmma::matrix_b, 16, 16, 16, __half, wmma::row_major> b;
                wmma::load_matrix_sync(b, sB + (kk * 16) * 72 + warpCol * 32 + j * 16, 72);
                wmma::mma_sync(acc[j], a, b, acc[j]);
            }
        }
    }

    #pragma unroll
    for (int j = 0; j < 2; j++)
        wmma::store_matrix_sync(
            gO + (size_t)(warpRow * 16) * SD_ + q * DK_ + warpCol * 32 + j * 16,
            acc[j], SD_, wmma::mem_row_major);
}

// ---------------------------------------------------------------------------
// Kernel 5: out = concat_heads(gO) @ Wp + bp. 3xbf16 split, tile 128x64.
// ---------------------------------------------------------------------------
__global__ __launch_bounds__(256)
void final_kernel(const float* __restrict__ Wp, const float* __restrict__ bp,
                  float* __restrict__ out)
{
    __shared__ float sBias[16 * 72];
    __shared__ __nv_bfloat16 sAhi[128 * 40], sAlo[128 * 40];
    __shared__ __nv_bfloat16 sBhi[32 * 72],  sBlo[32 * 72];

    const int tid = threadIdx.x;
    const int wid = tid >> 5;
    const int warpRow = wid >> 1;
    const int warpCol = wid & 1;
    const int m0 = blockIdx.y * 128;
    const int n0 = blockIdx.x * 64;
    const int bb = m0 >> 10;
    const int sBase = m0 & 1023;

    #pragma unroll
    for (int i = 0; i < 4; i++) {
        int idx = tid + i * 256;
        int r = idx >> 6, c = idx & 63;
        sBias[r * 72 + c] = bp[n0 + c];
    }
    __syncthreads();

    wmma::fragment<wmma::accumulator, 16, 16, 16, float> acc[2][2];
    #pragma unroll
    for (int mi = 0; mi < 2; mi++)
        #pragma unroll
        for (int ni = 0; ni < 2; ni++)
            wmma::load_matrix_sync(acc[mi][ni], sBias + warpCol * 32 + ni * 16,
                                   72, wmma::mem_row_major);

    for (int kt = 0; kt < 16; kt++) {
        const int k0 = kt * 32;
        const int h = k0 >> 6, d0 = k0 & 63;
        const float* Abase = gO + ((bb * H_ + h) << 16) + d0;
        #pragma unroll
        for (int i = 0; i < 4; i++) {
            int fi = tid + i * 256;
            int row = fi >> 3, c4 = (fi & 7) * 4;
            float4 v = *(const float4*)(Abase + (sBase + row) * DK_ + c4);
            __nv_bfloat16 hx = __float2bfloat16(v.x), hy = __float2bfloat16(v.y);
            __nv_bfloat16 hz = __float2bfloat16(v.z), hw = __float2bfloat16(v.w);
            __nv_bfloat162 h01(hx, hy), h23(hz, hw);
            __nv_bfloat162 l01(__float2bfloat16(v.x - __bfloat162float(hx)),
                               __float2bfloat16(v.y - __bfloat162float(hy)));
            __nv_bfloat162 l23(__float2bfloat16(v.z - __bfloat162float(hz)),
                               __float2bfloat16(v.w - __bfloat162float(hw)));
            *(__nv_bfloat162*)&sAhi[row * 40 + c4]     = h01;
            *(__nv_bfloat162*)&sAhi[row * 40 + c4 + 2] = h23;
            *(__nv_bfloat162*)&sAlo[row * 40 + c4]     = l01;
            *(__nv_bfloat162*)&sAlo[row * 40 + c4 + 2] = l23;
        }
        #pragma unroll
        for (int i = 0; i < 2; i++) {
            int fi = tid + i * 256;
            int row = fi >> 4, c4 = (fi & 15) * 4;
            float4 v = *(const float4*)(Wp + (k0 + row) * HD_ + n0 + c4);
            __nv_bfloat16 hx = __float2bfloat16(v.x), hy = __float2bfloat16(v.y);
            __nv_bfloat16 hz = __float2bfloat16(v.z), hw = __float2bfloat16(v.w);
            __nv_bfloat162 h01(hx, hy), h23(hz, hw);
            __nv_bfloat162 l01(__float2bfloat16(v.x - __bfloat162float(hx)),
                               __float2bfloat16(v.y - __bfloat162float(hy)));
            __nv_bfloat162 l23(__float2bfloat16(v.z - __bfloat162float(hz)),
                               __float2bfloat16(v.w - __bfloat162float(hw)));
            *(__nv_bfloat162*)&sBhi[row * 72 + c4]     = h01;
            *(__nv_bfloat162*)&sBhi[row * 72 + c4 + 2] = h23;
            *(__nv_bfloat162*)&sBlo[row * 72 + c4]     = l01;
            *(__nv_bfloat162*)&sBlo[row * 72 + c4 + 2] = l23;
        }
        __syncthreads();
        #pragma unroll
        for (int kk = 0; kk < 2; kk++) {
            wmma::fragment<wmma::matrix_b, 16, 16, 16, __nv_bfloat16, wmma::row_major> bhf[2], blf[2];
            #pragma unroll
            for (int ni = 0; ni < 2; ni++) {
                wmma::load_matrix_sync(bhf[ni], sBhi + (kk * 16) * 72 + warpCol * 32 + ni * 16, 72);
                wmma::load_matrix_sync(blf[ni], sBlo + (kk * 16) * 72 + warpCol * 32 + ni * 16, 72);
            }
            #pragma unroll
            for (int mi = 0; mi < 2; mi++) {
                wmma::fragment<wmma::matrix_a, 16, 16, 16, __nv_bfloat16, wmma::row_major> ah, al;
                wmma::load_matrix_sync(ah, sAhi + (warpRow * 32 + mi * 16) * 40 + kk * 16, 40);
                wmma::load_matrix_sync(al, sAlo + (warpRow * 32 + mi * 16) * 40 + kk * 16, 40);
                #pragma unroll
                for (int ni = 0; ni < 2; ni++) {
                    wmma::mma_sync(acc[mi][ni], ah, bhf[ni], acc[mi][ni]);
                    wmma::mma_sync(acc[mi][ni], ah, blf[ni], acc[mi][ni]);
                    wmma::mma_sync(acc[mi][ni], al, bhf[ni], acc[mi][ni]);
                }
            }
        }
        __syncthreads();
    }

    #pragma unroll
    for (int mi = 0; mi < 2; mi++)
        #pragma unroll
        for (int ni = 0; ni < 2; ni++)
            wmma::store_matrix_sync(
                out + (m0 + warpRow * 32 + mi * 16) * HD_ + n0 + warpCol * 32 + ni * 16,
                acc[mi][ni], HD_, wmma::mem_row_major);
}

// ---------------------------------------------------------------------------
extern "C" void kernel_launch(void* const* d_in, const int* in_sizes, int n_in,
                              void* d_out, int out_size)
{
    const float* queries = (const float*)d_in[0];
    const float* keys    = (const float*)d_in[1];
    const float* values  = (const float*)d_in[2];
    const float* Ek      = (const float*)d_in[3];
    const float* Ev      = (const float*)d_in[4];
    const float* abias   = (const float*)d_in[5];
    const float* Wq = (const float*)d_in[6];
    const float* bq = (const float*)d_in[7];
    const float* Wk = (const float*)d_in[8];
    const float* bk = (const float*)d_in[9];
    const float* Wv = (const float*)d_in[10];
    const float* bv = (const float*)d_in[11];
    const float* Wp = (const float*)d_in[12];
    const float* bp = (const float*)d_in[13];
    float* out = (float*)d_out;

    const int SMEM_EB = (2 * 64 * 68 + 64 * 72) * (int)sizeof(float);           // 53248
    const int SMEM_FA = (32 * 72 + 128 * 68 + 32 * TPAD) * (int)sizeof(float);  // 176128
    cudaFuncSetAttribute(edge_bias_kernel, cudaFuncAttributeMaxDynamicSharedMemorySize, SMEM_EB);
    cudaFuncSetAttribute(fused_attn_kernel, cudaFuncAttributeMaxDynamicSharedMemorySize, SMEM_FA);

    dim3 blk(256);
    proj_kernel<<<dim3(8, 64, 3), blk>>>(queries, keys, values, Wq, Wk, Wv, bq, bk, bv);
    edge_bias_kernel<<<dim3(16, 1024), blk, SMEM_EB>>>(Ek, abias);
    fused_attn_kernel<<<dim3(32, 64), blk, SMEM_FA>>>();
    edgev_kernel<<<1024, blk>>>(Ev);
    final_kernel<<<dim3(8, 64), blk>>>(Wp, bp, out);
}

// round 10
// speedup vs baseline: 1.6709x; 1.5958x over previous
#include <cuda_runtime.h>
#include <cuda_bf16.h>
#include <cuda_fp16.h>
#include <mma.h>

using namespace nvcuda;

constexpr int B_   = 8;
constexpr int H_   = 8;
constexpr int S_   = 1024;
constexpr int DK_  = 64;
constexpr int EMB_ = 512;
constexpr int HD_  = 512;   // H*DK
constexpr int BH_  = 64;    // B*H
constexpr int SD_  = S_ * DK_;   // 65536
constexpr int SS_  = S_ * S_;    // 1048576
constexpr int TP   = 1036;       // sT row stride in floats (odd*4+... keeps LDSM conflict-free)

// Scratch (device globals: allocation-free rule)
__device__ __half gQh[BH_ * S_ * DK_];  // fp16, q pre-scaled by 1/8
__device__ __half gKh[BH_ * S_ * DK_];
__device__ __half gVh[BH_ * S_ * DK_];
__device__ float  gO[BH_ * S_ * DK_];
// gS: fp32 score-bias before softmax; fp16 weights (row prefix) after softmax
__device__ float  gS[(size_t)BH_ * S_ * S_];

// ---------------------------------------------------------------------------
// Kernel 1: merged QKV projection, 3xbf16 split. Tile 128x64, k-chunk 32.
// Output fp16 to gQh/gKh/gVh in [B,H,S,DK].
// ---------------------------------------------------------------------------
__global__ __launch_bounds__(256)
void proj_kernel(const float* __restrict__ Xq, const float* __restrict__ Xk,
                 const float* __restrict__ Xv,
                 const float* __restrict__ Wq, const float* __restrict__ Wk,
                 const float* __restrict__ Wv,
                 const float* __restrict__ bq, const float* __restrict__ bk,
                 const float* __restrict__ bv)
{
    extern __shared__ char psm[];
    __nv_bfloat16* sAhi = (__nv_bfloat16*)psm;      // 128*40
    __nv_bfloat16* sAlo = sAhi + 128 * 40;
    __nv_bfloat16* sBhi = sAlo + 128 * 40;          // 32*72
    __nv_bfloat16* sBlo = sBhi + 32 * 72;
    float* sBias = (float*)(sBlo + 32 * 72);        // 16*72
    float* stage = (float*)psm;                     // epilogue reuse: 128*68

    const int which = blockIdx.z;
    const float* X    = (which == 0) ? Xq : (which == 1) ? Xk : Xv;
    const float* W    = (which == 0) ? Wq : (which == 1) ? Wk : Wv;
    const float* bias = (which == 0) ? bq : (which == 1) ? bk : bv;
    __half* outp      = (which == 0) ? gQh : (which == 1) ? gKh : gVh;
    const float scale = (which == 0) ? 0.125f : 1.0f;

    const int tid = threadIdx.x;
    const int wid = tid >> 5;
    const int warpRow = wid >> 1;   // 0..3
    const int warpCol = wid & 1;    // 0..1
    const int m0 = blockIdx.y * 128;
    const int n0 = blockIdx.x * 64;
    const int bb = m0 >> 10;
    const int sBase = m0 & 1023;
    const int h  = n0 >> 6;

    #pragma unroll
    for (int i = 0; i < 4; i++) {
        int idx = tid + i * 256;
        int r = idx >> 6, c = idx & 63;
        sBias[r * 72 + c] = bias[n0 + c];
    }
    __syncthreads();

    wmma::fragment<wmma::accumulator, 16, 16, 16, float> acc[2][2];
    #pragma unroll
    for (int mi = 0; mi < 2; mi++)
        #pragma unroll
        for (int ni = 0; ni < 2; ni++)
            wmma::load_matrix_sync(acc[mi][ni], sBias + warpCol * 32 + ni * 16,
                                   72, wmma::mem_row_major);
    __syncthreads();

    for (int kt = 0; kt < 16; kt++) {
        const int k0 = kt * 32;
        #pragma unroll
        for (int i = 0; i < 4; i++) {
            int fi = tid + i * 256;
            int row = fi >> 3, c4 = (fi & 7) * 4;
            float4 v = *(const float4*)(X + (m0 + row) * EMB_ + k0 + c4);
            __nv_bfloat16 hx = __float2bfloat16(v.x), hy = __float2bfloat16(v.y);
            __nv_bfloat16 hz = __float2bfloat16(v.z), hw = __float2bfloat16(v.w);
            *(__nv_bfloat162*)&sAhi[row * 40 + c4]     = __nv_bfloat162(hx, hy);
            *(__nv_bfloat162*)&sAhi[row * 40 + c4 + 2] = __nv_bfloat162(hz, hw);
            *(__nv_bfloat162*)&sAlo[row * 40 + c4] =
                __nv_bfloat162(__float2bfloat16(v.x - __bfloat162float(hx)),
                               __float2bfloat16(v.y - __bfloat162float(hy)));
            *(__nv_bfloat162*)&sAlo[row * 40 + c4 + 2] =
                __nv_bfloat162(__float2bfloat16(v.z - __bfloat162float(hz)),
                               __float2bfloat16(v.w - __bfloat162float(hw)));
        }
        #pragma unroll
        for (int i = 0; i < 2; i++) {
            int fi = tid + i * 256;
            int row = fi >> 4, c4 = (fi & 15) * 4;
            float4 v = *(const float4*)(W + (k0 + row) * HD_ + n0 + c4);
            __nv_bfloat16 hx = __float2bfloat16(v.x), hy = __float2bfloat16(v.y);
            __nv_bfloat16 hz = __float2bfloat16(v.z), hw = __float2bfloat16(v.w);
            *(__nv_bfloat162*)&sBhi[row * 72 + c4]     = __nv_bfloat162(hx, hy);
            *(__nv_bfloat162*)&sBhi[row * 72 + c4 + 2] = __nv_bfloat162(hz, hw);
            *(__nv_bfloat162*)&sBlo[row * 72 + c4] =
                __nv_bfloat162(__float2bfloat16(v.x - __bfloat162float(hx)),
                               __float2bfloat16(v.y - __bfloat162float(hy)));
            *(__nv_bfloat162*)&sBlo[row * 72 + c4 + 2] =
                __nv_bfloat162(__float2bfloat16(v.z - __bfloat162float(hz)),
                               __float2bfloat16(v.w - __bfloat162float(hw)));
        }
        __syncthreads();
        #pragma unroll
        for (int kk = 0; kk < 2; kk++) {
            wmma::fragment<wmma::matrix_b, 16, 16, 16, __nv_bfloat16, wmma::row_major> bhf[2], blf[2];
            #pragma unroll
            for (int ni = 0; ni < 2; ni++) {
                wmma::load_matrix_sync(bhf[ni], sBhi + (kk * 16) * 72 + warpCol * 32 + ni * 16, 72);
                wmma::load_matrix_sync(blf[ni], sBlo + (kk * 16) * 72 + warpCol * 32 + ni * 16, 72);
            }
            #pragma unroll
            for (int mi = 0; mi < 2; mi++) {
                wmma::fragment<wmma::matrix_a, 16, 16, 16, __nv_bfloat16, wmma::row_major> ah, al;
                wmma::load_matrix_sync(ah, sAhi + (warpRow * 32 + mi * 16) * 40 + kk * 16, 40);
                wmma::load_matrix_sync(al, sAlo + (warpRow * 32 + mi * 16) * 40 + kk * 16, 40);
                #pragma unroll
                for (int ni = 0; ni < 2; ni++) {
                    wmma::mma_sync(acc[mi][ni], ah, bhf[ni], acc[mi][ni]);
                    wmma::mma_sync(acc[mi][ni], ah, blf[ni], acc[mi][ni]);
                    wmma::mma_sync(acc[mi][ni], al, bhf[ni], acc[mi][ni]);
                }
            }
        }
        __syncthreads();
    }

    // Epilogue: scale, stage fp32, write fp16
    #pragma unroll
    for (int mi = 0; mi < 2; mi++)
        #pragma unroll
        for (int ni = 0; ni < 2; ni++) {
            #pragma unroll
            for (int e = 0; e < acc[mi][ni].num_elements; e++)
                acc[mi][ni].x[e] *= scale;
            wmma::store_matrix_sync(stage + (warpRow * 32 + mi * 16) * 68 + warpCol * 32 + ni * 16,
                                    acc[mi][ni], 68, wmma::mem_row_major);
        }
    __syncthreads();
    __half* obase = outp + ((size_t)((bb * H_ + h) << 16));
    #pragma unroll
    for (int i = 0; i < 16; i++) {
        int idx = tid + i * 256;
        int r = idx >> 5, cp = (idx & 31) * 2;
        float2 v = *(float2*)(stage + r * 68 + cp);
        *(__half2*)(obase + (size_t)(sBase + r) * DK_ + cp) = __floats2half2_rn(v.x, v.y);
    }
}

// ---------------------------------------------------------------------------
// Kernel 2: gS[bh,q,n] = gQh[bh,q,:]·Ek[q,n,:] + abias[b,q,n]. fp16 MMA.
// ---------------------------------------------------------------------------
__global__ __launch_bounds__(256, 4)
void edge_bias_kernel(const float* __restrict__ Ek, const float* __restrict__ abias)
{
    extern __shared__ char esm[];
    __half* sA  = (__half*)esm;          // 64 x 72 (row=bh, col=d)
    __half* sEk = sA + 64 * 72;          // 64 x 72 (row=n, col=d)
    float* sBias = (float*)(sEk + 64 * 72);  // 64 x 72

    const int tid = threadIdx.x;
    const int wid = tid >> 5;
    const int wr  = wid >> 2;            // 0..1
    const int wc  = wid & 3;             // 0..3 -> 16 cols
    const int q   = blockIdx.y;
    const int n0  = blockIdx.x * 64;
    const int rowA = tid >> 4;           // 0..15
    const int c4   = (tid & 15) * 4;

    #pragma unroll
    for (int i = 0; i < 4; i++) {
        int row = rowA + i * 16;
        *(uint2*)&sA[row * 72 + c4] =
            *(const uint2*)(gQh + (size_t)row * SD_ + q * DK_ + c4);
        float4 v = *(const float4*)(Ek + ((size_t)q * S_ + n0 + row) * DK_ + c4);
        *(__half2*)&sEk[row * 72 + c4]     = __floats2half2_rn(v.x, v.y);
        *(__half2*)&sEk[row * 72 + c4 + 2] = __floats2half2_rn(v.z, v.w);
    }
    #pragma unroll
    for (int i = 0; i < 16; i++) {
        int idx = tid + i * 256;
        int r = idx >> 6, c = idx & 63;
        sBias[r * 72 + c] = abias[(size_t)(r >> 3) * SS_ + (size_t)q * S_ + n0 + c];
    }
    __syncthreads();

    wmma::fragment<wmma::accumulator, 16, 16, 16, float> acc[2];
    #pragma unroll
    for (int mi = 0; mi < 2; mi++)
        wmma::load_matrix_sync(acc[mi], sBias + (wr * 32 + mi * 16) * 72 + wc * 16,
                               72, wmma::mem_row_major);

    #pragma unroll
    for (int kk = 0; kk < 4; kk++) {
        wmma::fragment<wmma::matrix_b, 16, 16, 16, __half, wmma::col_major> b;
        wmma::load_matrix_sync(b, sEk + (wc * 16) * 72 + kk * 16, 72);
        #pragma unroll
        for (int mi = 0; mi < 2; mi++) {
            wmma::fragment<wmma::matrix_a, 16, 16, 16, __half, wmma::row_major> a;
            wmma::load_matrix_sync(a, sA + (wr * 32 + mi * 16) * 72 + kk * 16, 72);
            wmma::mma_sync(acc[mi], a, b, acc[mi]);
        }
    }

    #pragma unroll
    for (int mi = 0; mi < 2; mi++)
        wmma::store_matrix_sync(
            gS + (size_t)(wr * 32 + mi * 16) * SS_ + (size_t)q * S_ + n0 + wc * 16,
            acc[mi], SS_, wmma::mem_row_major);
}

// ---------------------------------------------------------------------------
// Kernel 3 (FUSED): fp16 QK^T -> +bias -> softmax (register-resident)
//                   -> fp16 weights into sT rows + gS -> fp16 W @ V -> gO.
// ---------------------------------------------------------------------------
__global__ __launch_bounds__(256, 1)
void fused_attn_kernel()
{
    extern __shared__ char fsm[];
    __half* sQ  = (__half*)fsm;              // 32 x 72
    __half* sKV = sQ + 32 * 72;              // 128 x 72
    float*  sT  = (float*)(sKV + 128 * 72);  // 32 x TP

    const int tid = threadIdx.x;
    const int wid = tid >> 5;
    const int lane = tid & 31;
    const int bh = blockIdx.y;
    const int q0 = blockIdx.x * 32;
    const int rowA = tid >> 4;               // 0..15
    const int c4   = (tid & 15) * 4;         // half-index

    #pragma unroll
    for (int i = 0; i < 2; i++) {
        int fi = tid + i * 256;
        int row = fi >> 4, cc = (fi & 15) * 4;
        *(uint2*)&sQ[row * 72 + cc] =
            *(const uint2*)(gQh + (size_t)bh * SD_ + (q0 + row) * DK_ + cc);
    }
    __syncthreads();

    // ---- Phase A: raw scores, fp16 MMA ----
    {
        const int wr = wid >> 2;   // 0..1
        const int wc = wid & 3;    // 0..3
        wmma::fragment<wmma::matrix_a, 16, 16, 16, __half, wmma::row_major> a[4];
        #pragma unroll
        for (int kk = 0; kk < 4; kk++)
            wmma::load_matrix_sync(a[kk], sQ + (wr * 16) * 72 + kk * 16, 72);

        const __half* Kbase = gKh + (size_t)bh * SD_;

        uint2 pK[8];
        #pragma unroll
        for (int i = 0; i < 8; i++)
            pK[i] = *(const uint2*)(Kbase + (rowA + i * 16) * DK_ + c4);

        for (int nc = 0; nc < 8; nc++) {
            __syncthreads();
            #pragma unroll
            for (int i = 0; i < 8; i++)
                *(uint2*)&sKV[(rowA + i * 16) * 72 + c4] = pK[i];
            __syncthreads();
            if (nc < 7) {
                const int n1 = (nc + 1) * 128;
                #pragma unroll
                for (int i = 0; i < 8; i++)
                    pK[i] = *(const uint2*)(Kbase + (n1 + rowA + i * 16) * DK_ + c4);
            }
            #pragma unroll
            for (int ni = 0; ni < 2; ni++) {
                const int ncol = wc * 32 + ni * 16;
                wmma::fragment<wmma::accumulator, 16, 16, 16, float> acc;
                wmma::fill_fragment(acc, 0.0f);
                #pragma unroll
                for (int kk = 0; kk < 4; kk++) {
                    wmma::fragment<wmma::matrix_b, 16, 16, 16, __half, wmma::col_major> b;
                    wmma::load_matrix_sync(b, sKV + ncol * 72 + kk * 16, 72);
                    wmma::mma_sync(acc, a[kk], b, acc);
                }
                wmma::store_matrix_sync(sT + (wr * 16) * TP + nc * 128 + ncol,
                                        acc, TP, wmma::mem_row_major);
            }
        }
    }
    __syncthreads();

    // ---- Phase B: +bias, softmax in registers; fp16 weights -> own sT row + gS ----
    #pragma unroll
    for (int rr = 0; rr < 4; rr++) {
        int r = wid * 4 + rr;
        float* row = sT + r * TP;
        float* grow = gS + ((size_t)bh * S_ + q0 + r) * S_;
        float vals[32];
        float mx = -3.0e38f;
        #pragma unroll
        for (int j = 0; j < 32; j++) {
            float v = row[lane + 32 * j] + grow[lane + 32 * j];
            vals[j] = v;
            mx = fmaxf(mx, v);
        }
        #pragma unroll
        for (int o = 16; o; o >>= 1) mx = fmaxf(mx, __shfl_xor_sync(0xffffffffu, mx, o));
        float sum = 0.0f;
        #pragma unroll
        for (int j = 0; j < 32; j++) {
            float e = expf(vals[j] - mx);
            vals[j] = e;
            sum += e;
        }
        #pragma unroll
        for (int o = 16; o; o >>= 1) sum += __shfl_xor_sync(0xffffffffu, sum, o);
        float inv = 1.0f / sum;
        __half* hrow = (__half*)row;   // fp32 scores in this row are dead now
        #pragma unroll
        for (int j = 0; j < 32; j++)
            hrow[lane + 32 * j] = __float2half_rn(vals[j] * inv);
        __syncwarp();
        // coalesced copy of fp16 weights to gS
        const unsigned int* hsrc = (const unsigned int*)hrow;
        unsigned int* gdst = (unsigned int*)grow;
        #pragma unroll
        for (int j = 0; j < 16; j++)
            gdst[lane + 32 * j] = hsrc[lane + 32 * j];
    }
    __syncthreads();

    // ---- Phase C: out = weights @ V, fp16 MMA ----
    {
        const int wr = wid >> 2;   // 0..1
        const int wc = wid & 3;    // 0..3
        wmma::fragment<wmma::accumulator, 16, 16, 16, float> c[2];
        wmma::fill_fragment(c[0], 0.0f);
        wmma::fill_fragment(c[1], 0.0f);
        const __half* Vbase = gVh + (size_t)bh * SD_;
        const __half* Tbase = (const __half*)(sT + (wr * 16) * TP);
        const int tldm = TP * 2;   // half elements per sT row

        uint2 pV[4];
        #pragma unroll
        for (int i = 0; i < 4; i++)
            pV[i] = *(const uint2*)(Vbase + (rowA + i * 16) * DK_ + c4);

        for (int kt = 0; kt < 16; kt++) {
            __syncthreads();
            #pragma unroll
            for (int i = 0; i < 4; i++)
                *(uint2*)&sKV[(rowA + i * 16) * 72 + c4] = pV[i];
            __syncthreads();
            if (kt < 15) {
                const int k1 = (kt + 1) * 64;
                #pragma unroll
                for (int i = 0; i < 4; i++)
                    pV[i] = *(const uint2*)(Vbase + (k1 + rowA + i * 16) * DK_ + c4);
            }
            #pragma unroll
            for (int kk = 0; kk < 4; kk++) {
                wmma::fragment<wmma::matrix_a, 16, 16, 16, __half, wmma::row_major> a;
                wmma::fragment<wmma::matrix_b, 16, 16, 16, __half, wmma::row_major> b;
                wmma::load_matrix_sync(a, Tbase + kt * 64 + kk * 16, tldm);
                wmma::load_matrix_sync(b, sKV + (kk * 16) * 72 + wc * 16, 72);
                wmma::mma_sync(c[kk & 1], a, b, c[kk & 1]);
            }
        }
        #pragma unroll
        for (int e = 0; e < c[0].num_elements; e++) c[0].x[e] += c[1].x[e];
        wmma::store_matrix_sync(gO + (size_t)bh * SD_ + (q0 + wr * 16) * DK_ + wc * 16,
                                c[0], DK_, wmma::mem_row_major);
    }
}

// ---------------------------------------------------------------------------
// Kernel 4: gO += weights[:,q,:] @ Ev[q].  fp16 MMA, fp16 weights from gS.
// ---------------------------------------------------------------------------
__global__ __launch_bounds__(256, 4)
void edgev_kernel(const float* __restrict__ Ev)
{
    __shared__ __half sA[64 * 72];
    __shared__ __half sB[64 * 72];

    const int tid = threadIdx.x;
    const int wid = tid >> 5;
    const int warpRow = wid >> 1;   // 0..3
    const int warpCol = wid & 1;    // 0..1
    const int q = blockIdx.x;
    const int rowA = tid >> 4;      // 0..15
    const int c4   = (tid & 15) * 4;

    wmma::fragment<wmma::accumulator, 16, 16, 16, float> acc[2];
    #pragma unroll
    for (int j = 0; j < 2; j++)
        wmma::load_matrix_sync(acc[j],
            gO + (size_t)(warpRow * 16) * SD_ + q * DK_ + warpCol * 32 + j * 16,
            SD_, wmma::mem_row_major);

    uint2  pA[4];
    float4 pB[4];
    #pragma unroll
    for (int i = 0; i < 4; i++) {
        int row = rowA + i * 16;
        pA[i] = *(const uint2*)((const __half*)(gS + (size_t)row * SS_ + (size_t)q * S_) + c4);
        pB[i] = *(const float4*)(Ev + ((size_t)q * S_ + row) * DK_ + c4);
    }

    for (int kt = 0; kt < 16; kt++) {
        __syncthreads();
        #pragma unroll
        for (int i = 0; i < 4; i++) {
            int row = rowA + i * 16;
            *(uint2*)&sA[row * 72 + c4] = pA[i];
            float4 v = pB[i];
            *(__half2*)&sB[row * 72 + c4]     = __floats2half2_rn(v.x, v.y);
            *(__half2*)&sB[row * 72 + c4 + 2] = __floats2half2_rn(v.z, v.w);
        }
        __syncthreads();
        if (kt < 15) {
            const int k1 = (kt + 1) * 64;
            #pragma unroll
            for (int i = 0; i < 4; i++) {
                int row = rowA + i * 16;
                pA[i] = *(const uint2*)((const __half*)(gS + (size_t)row * SS_ + (size_t)q * S_) + k1 + c4);
                pB[i] = *(const float4*)(Ev + ((size_t)q * S_ + k1 + row) * DK_ + c4);
            }
        }
        #pragma unroll
        for (int kk = 0; kk < 4; kk++) {
            wmma::fragment<wmma::matrix_a, 16, 16, 16, __half, wmma::row_major> a;
            wmma::load_matrix_sync(a, sA + (warpRow * 16) * 72 + kk * 16, 72);
            #pragma unroll
            for (int j = 0; j < 2; j++) {
                wmma::fragment<wmma::matrix_b, 16, 16, 16, __half, wmma::row_major> b;
                wmma::load_matrix_sync(b, sB + (kk * 16) * 72 + warpCol * 32 + j * 16, 72);
                wmma::mma_sync(acc[j], a, b, acc[j]);
            }
        }
    }

    #pragma unroll
    for (int j = 0; j < 2; j++)
        wmma::store_matrix_sync(
            gO + (size_t)(warpRow * 16) * SD_ + q * DK_ + warpCol * 32 + j * 16,
            acc[j], SD_, wmma::mem_row_major);
}

// ---------------------------------------------------------------------------
// Kernel 5: out = concat_heads(gO) @ Wp + bp. 3xbf16 split, tile 128x64.
// ---------------------------------------------------------------------------
__global__ __launch_bounds__(256)
void final_kernel(const float* __restrict__ Wp, const float* __restrict__ bp,
                  float* __restrict__ out)
{
    __shared__ float sBias[16 * 72];
    __shared__ __nv_bfloat16 sAhi[128 * 40], sAlo[128 * 40];
    __shared__ __nv_bfloat16 sBhi[32 * 72],  sBlo[32 * 72];

    const int tid = threadIdx.x;
    const int wid = tid >> 5;
    const int warpRow = wid >> 1;
    const int warpCol = wid & 1;
    const int m0 = blockIdx.y * 128;
    const int n0 = blockIdx.x * 64;
    const int bb = m0 >> 10;
    const int sBase = m0 & 1023;

    #pragma unroll
    for (int i = 0; i < 4; i++) {
        int idx = tid + i * 256;
        int r = idx >> 6, c = idx & 63;
        sBias[r * 72 + c] = bp[n0 + c];
    }
    __syncthreads();

    wmma::fragment<wmma::accumulator, 16, 16, 16, float> acc[2][2];
    #pragma unroll
    for (int mi = 0; mi < 2; mi++)
        #pragma unroll
        for (int ni = 0; ni < 2; ni++)
            wmma::load_matrix_sync(acc[mi][ni], sBias + warpCol * 32 + ni * 16,
                                   72, wmma::mem_row_major);

    for (int kt = 0; kt < 16; kt++) {
        const int k0 = kt * 32;
        const int h = k0 >> 6, d0 = k0 & 63;
        const float* Abase = gO + ((size_t)((bb * H_ + h) << 16)) + d0;
        #pragma unroll
        for (int i = 0; i < 4; i++) {
            int fi = tid + i * 256;
            int row = fi >> 3, c4 = (fi & 7) * 4;
            float4 v = *(const float4*)(Abase + (size_t)(sBase + row) * DK_ + c4);
            __nv_bfloat16 hx = __float2bfloat16(v.x), hy = __float2bfloat16(v.y);
            __nv_bfloat16 hz = __float2bfloat16(v.z), hw = __float2bfloat16(v.w);
            *(__nv_bfloat162*)&sAhi[row * 40 + c4]     = __nv_bfloat162(hx, hy);
            *(__nv_bfloat162*)&sAhi[row * 40 + c4 + 2] = __nv_bfloat162(hz, hw);
            *(__nv_bfloat162*)&sAlo[row * 40 + c4] =
                __nv_bfloat162(__float2bfloat16(v.x - __bfloat162float(hx)),
                               __float2bfloat16(v.y - __bfloat162float(hy)));
            *(__nv_bfloat162*)&sAlo[row * 40 + c4 + 2] =
                __nv_bfloat162(__float2bfloat16(v.z - __bfloat162float(hz)),
                               __float2bfloat16(v.w - __bfloat162float(hw)));
        }
        #pragma unroll
        for (int i = 0; i < 2; i++) {
            int fi = tid + i * 256;
            int row = fi >> 4, c4 = (fi & 15) * 4;
            float4 v = *(const float4*)(Wp + (k0 + row) * HD_ + n0 + c4);
            __nv_bfloat16 hx = __float2bfloat16(v.x), hy = __float2bfloat16(v.y);
            __nv_bfloat16 hz = __float2bfloat16(v.z), hw = __float2bfloat16(v.w);
            *(__nv_bfloat162*)&sBhi[row * 72 + c4]     = __nv_bfloat162(hx, hy);
            *(__nv_bfloat162*)&sBhi[row * 72 + c4 + 2] = __nv_bfloat162(hz, hw);
            *(__nv_bfloat162*)&sBlo[row * 72 + c4] =
                __nv_bfloat162(__float2bfloat16(v.x - __bfloat162float(hx)),
                               __float2bfloat16(v.y - __bfloat162float(hy)));
            *(__nv_bfloat162*)&sBlo[row * 72 + c4 + 2] =
                __nv_bfloat162(__float2bfloat16(v.z - __bfloat162float(hz)),
                               __float2bfloat16(v.w - __bfloat162float(hw)));
        }
        __syncthreads();
        #pragma unroll
        for (int kk = 0; kk < 2; kk++) {
            wmma::fragment<wmma::matrix_b, 16, 16, 16, __nv_bfloat16, wmma::row_major> bhf[2], blf[2];
            #pragma unroll
            for (int ni = 0; ni < 2; ni++) {
                wmma::load_matrix_sync(bhf[ni], sBhi + (kk * 16) * 72 + warpCol * 32 + ni * 16, 72);
                wmma::load_matrix_sync(blf[ni], sBlo + (kk * 16) * 72 + warpCol * 32 + ni * 16, 72);
            }
            #pragma unroll
            for (int mi = 0; mi < 2; mi++) {
                wmma::fragment<wmma::matrix_a, 16, 16, 16, __nv_bfloat16, wmma::row_major> ah, al;
                wmma::load_matrix_sync(ah, sAhi + (warpRow * 32 + mi * 16) * 40 + kk * 16, 40);
                wmma::load_matrix_sync(al, sAlo + (warpRow * 32 + mi * 16) * 40 + kk * 16, 40);
                #pragma unroll
                for (int ni = 0; ni < 2; ni++) {
                    wmma::mma_sync(acc[mi][ni], ah, bhf[ni], acc[mi][ni]);
                    wmma::mma_sync(acc[mi][ni], ah, blf[ni], acc[mi][ni]);
                    wmma::mma_sync(acc[mi][ni], al, bhf[ni], acc[mi][ni]);
                }
            }
        }
        __syncthreads();
    }

    #pragma unroll
    for (int mi = 0; mi < 2; mi++)
        #pragma unroll
        for (int ni = 0; ni < 2; ni++)
            wmma::store_matrix_sync(
                out + (size_t)(m0 + warpRow * 32 + mi * 16) * HD_ + n0 + warpCol * 32 + ni * 16,
                acc[mi][ni], HD_, wmma::mem_row_major);
}

// ---------------------------------------------------------------------------
extern "C" void kernel_launch(void* const* d_in, const int* in_sizes, int n_in,
                              void* d_out, int out_size)
{
    const float* queries = (const float*)d_in[0];
    const float* keys    = (const float*)d_in[1];
    const float* values  = (const float*)d_in[2];
    const float* Ek      = (const float*)d_in[3];
    const float* Ev      = (const float*)d_in[4];
    const float* abias   = (const float*)d_in[5];
    const float* Wq = (const float*)d_in[6];
    const float* bq = (const float*)d_in[7];
    const float* Wk = (const float*)d_in[8];
    const float* bk = (const float*)d_in[9];
    const float* Wv = (const float*)d_in[10];
    const float* bv = (const float*)d_in[11];
    const float* Wp = (const float*)d_in[12];
    const float* bp = (const float*)d_in[13];
    float* out = (float*)d_out;

    const int SMEM_PR = 128 * 68 * 4;                                   // 34816 (>= load bufs)
    const int SMEM_EB = 2 * 64 * 72 * 2 + 64 * 72 * 4;                  // 36864
    const int SMEM_FA = (32 * 72 + 128 * 72) * 2 + 32 * TP * 4;         // 155648
    cudaFuncSetAttribute(fused_attn_kernel, cudaFuncAttributeMaxDynamicSharedMemorySize, SMEM_FA);

    dim3 blk(256);
    proj_kernel<<<dim3(8, 64, 3), blk, SMEM_PR>>>(queries, keys, values, Wq, Wk, Wv, bq, bk, bv);
    edge_bias_kernel<<<dim3(16, 1024), blk, SMEM_EB>>>(Ek, abias);
    fused_attn_kernel<<<dim3(32, 64), blk, SMEM_FA>>>();
    edgev_kernel<<<1024, blk>>>(Ev);
    final_kernel<<<dim3(8, 64), blk>>>(Wp, bp, out);
}

// round 12
// speedup vs baseline: 2.2186x; 1.3278x over previous
#include <cuda_runtime.h>
#include <cuda_bf16.h>
#include <cuda_fp16.h>
#include <mma.h>

using namespace nvcuda;

constexpr int B_   = 8;
constexpr int H_   = 8;
constexpr int S_   = 1024;
constexpr int DK_  = 64;
constexpr int EMB_ = 512;
constexpr int HD_  = 512;   // H*DK
constexpr int BH_  = 64;    // B*H
constexpr int SD_  = S_ * DK_;   // 65536
constexpr int SS_  = S_ * S_;    // 1048576
constexpr int TP   = 1036;       // sT row stride in floats

// Scratch (device globals: allocation-free rule)
__device__ __half gQh[BH_ * S_ * DK_];  // fp16, q pre-scaled by 1/8
__device__ __half gKh[BH_ * S_ * DK_];
__device__ __half gVh[BH_ * S_ * DK_];
__device__ float  gO[BH_ * S_ * DK_];
// gS (fp16, 128MB): score-bias before softmax; attention weights after softmax
__device__ __half gS[(size_t)BH_ * S_ * S_];

// ---------------------------------------------------------------------------
// Kernel 1: merged QKV projection, single fp16 MMA. Tile 128x64, k-chunk 64.
// ---------------------------------------------------------------------------
__global__ __launch_bounds__(256)
void proj_kernel(const float* __restrict__ Xq, const float* __restrict__ Xk,
                 const float* __restrict__ Xv,
                 const float* __restrict__ Wq, const float* __restrict__ Wk,
                 const float* __restrict__ Wv,
                 const float* __restrict__ bq, const float* __restrict__ bk,
                 const float* __restrict__ bv)
{
    extern __shared__ char psm[];
    __half* sA = (__half*)psm;               // 128 x 72
    __half* sB = sA + 128 * 72;              // 64 x 72
    float* sBias = (float*)(sB + 64 * 72);   // 16 x 72
    float* stage = (float*)psm;              // epilogue reuse: 128 x 68

    const int which = blockIdx.z;
    const float* X    = (which == 0) ? Xq : (which == 1) ? Xk : Xv;
    const float* W    = (which == 0) ? Wq : (which == 1) ? Wk : Wv;
    const float* bias = (which == 0) ? bq : (which == 1) ? bk : bv;
    __half* outp      = (which == 0) ? gQh : (which == 1) ? gKh : gVh;
    const float scale = (which == 0) ? 0.125f : 1.0f;

    const int tid = threadIdx.x;
    const int wid = tid >> 5;
    const int warpRow = wid >> 1;   // 0..3
    const int warpCol = wid & 1;    // 0..1
    const int m0 = blockIdx.y * 128;
    const int n0 = blockIdx.x * 64;
    const int bb = m0 >> 10;
    const int sBase = m0 & 1023;
    const int h  = n0 >> 6;

    #pragma unroll
    for (int i = 0; i < 4; i++) {
        int idx = tid + i * 256;
        int r = idx >> 6, c = idx & 63;
        sBias[r * 72 + c] = bias[n0 + c];
    }
    __syncthreads();

    wmma::fragment<wmma::accumulator, 16, 16, 16, float> acc[2][2];
    #pragma unroll
    for (int mi = 0; mi < 2; mi++)
        #pragma unroll
        for (int ni = 0; ni < 2; ni++)
            wmma::load_matrix_sync(acc[mi][ni], sBias + warpCol * 32 + ni * 16,
                                   72, wmma::mem_row_major);
    __syncthreads();

    for (int kt = 0; kt < 8; kt++) {
        const int k0 = kt * 64;
        #pragma unroll
        for (int i = 0; i < 8; i++) {
            int fi = tid + i * 256;
            int row = fi >> 4, c4 = (fi & 15) * 4;
            float4 v = *(const float4*)(X + (m0 + row) * EMB_ + k0 + c4);
            *(__half2*)&sA[row * 72 + c4]     = __floats2half2_rn(v.x, v.y);
            *(__half2*)&sA[row * 72 + c4 + 2] = __floats2half2_rn(v.z, v.w);
        }
        #pragma unroll
        for (int i = 0; i < 4; i++) {
            int fi = tid + i * 256;
            int row = fi >> 4, c4 = (fi & 15) * 4;
            float4 v = *(const float4*)(W + (k0 + row) * HD_ + n0 + c4);
            *(__half2*)&sB[row * 72 + c4]     = __floats2half2_rn(v.x, v.y);
            *(__half2*)&sB[row * 72 + c4 + 2] = __floats2half2_rn(v.z, v.w);
        }
        __syncthreads();
        #pragma unroll
        for (int kk = 0; kk < 4; kk++) {
            wmma::fragment<wmma::matrix_b, 16, 16, 16, __half, wmma::row_major> bf[2];
            #pragma unroll
            for (int ni = 0; ni < 2; ni++)
                wmma::load_matrix_sync(bf[ni], sB + (kk * 16) * 72 + warpCol * 32 + ni * 16, 72);
            #pragma unroll
            for (int mi = 0; mi < 2; mi++) {
                wmma::fragment<wmma::matrix_a, 16, 16, 16, __half, wmma::row_major> a;
                wmma::load_matrix_sync(a, sA + (warpRow * 32 + mi * 16) * 72 + kk * 16, 72);
                #pragma unroll
                for (int ni = 0; ni < 2; ni++)
                    wmma::mma_sync(acc[mi][ni], a, bf[ni], acc[mi][ni]);
            }
        }
        __syncthreads();
    }

    // Epilogue: scale, stage fp32, write fp16
    #pragma unroll
    for (int mi = 0; mi < 2; mi++)
        #pragma unroll
        for (int ni = 0; ni < 2; ni++) {
            #pragma unroll
            for (int e = 0; e < acc[mi][ni].num_elements; e++)
                acc[mi][ni].x[e] *= scale;
            wmma::store_matrix_sync(stage + (warpRow * 32 + mi * 16) * 68 + warpCol * 32 + ni * 16,
                                    acc[mi][ni], 68, wmma::mem_row_major);
        }
    __syncthreads();
    __half* obase = outp + ((size_t)((bb * H_ + h) << 16));
    #pragma unroll
    for (int i = 0; i < 16; i++) {
        int idx = tid + i * 256;
        int r = idx >> 5, cp = (idx & 31) * 2;
        float2 v = *(float2*)(stage + r * 68 + cp);
        *(__half2*)(obase + (size_t)(sBase + r) * DK_ + cp) = __floats2half2_rn(v.x, v.y);
    }
}

// ---------------------------------------------------------------------------
// Kernel 2: gS[bh,q,n] = gQh[bh,q,:]·Ek[q,n,:] + abias[b,q,n]. fp16 MMA,
// fp16 output to gS.
// ---------------------------------------------------------------------------
__global__ __launch_bounds__(256, 4)
void edge_bias_kernel(const float* __restrict__ Ek, const float* __restrict__ abias)
{
    extern __shared__ char esm[];
    __half* sA  = (__half*)esm;              // 64 x 72 (row=bh, col=d)
    __half* sEk = sA + 64 * 72;              // 64 x 72 (row=n, col=d)
    float* sBias = (float*)(sEk + 64 * 72);  // 64 x 72 (bias; reused as stage)

    const int tid = threadIdx.x;
    const int wid = tid >> 5;
    const int wr  = wid >> 2;            // 0..1
    const int wc  = wid & 3;             // 0..3 -> 16 cols
    const int q   = blockIdx.y;
    const int n0  = blockIdx.x * 64;
    const int rowA = tid >> 4;           // 0..15
    const int c4   = (tid & 15) * 4;

    #pragma unroll
    for (int i = 0; i < 4; i++) {
        int row = rowA + i * 16;
        *(uint2*)&sA[row * 72 + c4] =
            *(const uint2*)(gQh + (size_t)row * SD_ + q * DK_ + c4);
        float4 v = *(const float4*)(Ek + ((size_t)q * S_ + n0 + row) * DK_ + c4);
        *(__half2*)&sEk[row * 72 + c4]     = __floats2half2_rn(v.x, v.y);
        *(__half2*)&sEk[row * 72 + c4 + 2] = __floats2half2_rn(v.z, v.w);
    }
    #pragma unroll
    for (int i = 0; i < 16; i++) {
        int idx = tid + i * 256;
        int r = idx >> 6, c = idx & 63;
        sBias[r * 72 + c] = abias[(size_t)(r >> 3) * SS_ + (size_t)q * S_ + n0 + c];
    }
    __syncthreads();

    wmma::fragment<wmma::accumulator, 16, 16, 16, float> acc[2];
    #pragma unroll
    for (int mi = 0; mi < 2; mi++)
        wmma::load_matrix_sync(acc[mi], sBias + (wr * 32 + mi * 16) * 72 + wc * 16,
                               72, wmma::mem_row_major);

    #pragma unroll
    for (int kk = 0; kk < 4; kk++) {
        wmma::fragment<wmma::matrix_b, 16, 16, 16, __half, wmma::col_major> b;
        wmma::load_matrix_sync(b, sEk + (wc * 16) * 72 + kk * 16, 72);
        #pragma unroll
        for (int mi = 0; mi < 2; mi++) {
            wmma::fragment<wmma::matrix_a, 16, 16, 16, __half, wmma::row_major> a;
            wmma::load_matrix_sync(a, sA + (wr * 32 + mi * 16) * 72 + kk * 16, 72);
            wmma::mma_sync(acc[mi], a, b, acc[mi]);
        }
    }

    __syncthreads();   // all warps done reading sBias for acc init
    #pragma unroll
    for (int mi = 0; mi < 2; mi++)
        wmma::store_matrix_sync(sBias + (wr * 32 + mi * 16) * 72 + wc * 16,
                                acc[mi], 72, wmma::mem_row_major);
    __syncthreads();
    #pragma unroll
    for (int i = 0; i < 8; i++) {
        int idx = tid + i * 256;
        int r = idx >> 5, u = idx & 31;
        float2 f = *(float2*)(sBias + r * 72 + 2 * u);
        ((__half2*)(gS + (size_t)r * SS_ + (size_t)q * S_ + n0))[u] =
            __floats2half2_rn(f.x, f.y);
    }
}

// ---------------------------------------------------------------------------
// Kernel 3 (FUSED): 16 q-rows/CTA, 2 CTAs/SM. fp16 QK^T -> +fp16 bias ->
// softmax (register) -> fp16 weights into sT + gS -> fp16 W @ V -> gO.
// ---------------------------------------------------------------------------
__global__ __launch_bounds__(256, 2)
void fused_attn_kernel()
{
    extern __shared__ char fsm[];
    __half* sQ  = (__half*)fsm;              // 16 x 72
    __half* sKV = sQ + 16 * 72;              // 128 x 72
    float*  sT  = (float*)(sKV + 128 * 72);  // 16 x TP

    const int tid = threadIdx.x;
    const int wid = tid >> 5;
    const int lane = tid & 31;
    const int bh = blockIdx.y;
    const int q0 = blockIdx.x * 16;
    const int rowA = tid >> 4;               // 0..15
    const int c4   = (tid & 15) * 4;         // half-index

    {
        int row = tid >> 4, cc = (tid & 15) * 4;
        *(uint2*)&sQ[row * 72 + cc] =
            *(const uint2*)(gQh + (size_t)bh * SD_ + (q0 + row) * DK_ + cc);
    }
    __syncthreads();

    // ---- Phase A: raw scores, fp16 MMA. warp wid owns 16 cols per 128-chunk ----
    {
        wmma::fragment<wmma::matrix_a, 16, 16, 16, __half, wmma::row_major> a[4];
        #pragma unroll
        for (int kk = 0; kk < 4; kk++)
            wmma::load_matrix_sync(a[kk], sQ + kk * 16, 72);

        const __half* Kbase = gKh + (size_t)bh * SD_;
        uint2 pK[8];
        #pragma unroll
        for (int i = 0; i < 8; i++)
            pK[i] = *(const uint2*)(Kbase + (rowA + i * 16) * DK_ + c4);

        for (int nc = 0; nc < 8; nc++) {
            __syncthreads();
            #pragma unroll
            for (int i = 0; i < 8; i++)
                *(uint2*)&sKV[(rowA + i * 16) * 72 + c4] = pK[i];
            __syncthreads();
            if (nc < 7) {
                const int n1 = (nc + 1) * 128;
                #pragma unroll
                for (int i = 0; i < 8; i++)
                    pK[i] = *(const uint2*)(Kbase + (n1 + rowA + i * 16) * DK_ + c4);
            }
            const int ncol = wid * 16;
            wmma::fragment<wmma::accumulator, 16, 16, 16, float> acc;
            wmma::fill_fragment(acc, 0.0f);
            #pragma unroll
            for (int kk = 0; kk < 4; kk++) {
                wmma::fragment<wmma::matrix_b, 16, 16, 16, __half, wmma::col_major> b;
                wmma::load_matrix_sync(b, sKV + ncol * 72 + kk * 16, 72);
                wmma::mma_sync(acc, a[kk], b, acc);
            }
            wmma::store_matrix_sync(sT + nc * 128 + ncol, acc, TP, wmma::mem_row_major);
        }
    }
    __syncthreads();

    // ---- Phase B: +fp16 bias, softmax in registers; fp16 weights -> sT + gS ----
    #pragma unroll
    for (int rr = 0; rr < 2; rr++) {
        int r = wid * 2 + rr;
        float* row = sT + r * TP;
        __half2* gb = (__half2*)(gS + ((size_t)bh * S_ + q0 + r) * S_);
        float vals[32];
        float mx = -3.0e38f;
        #pragma unroll
        for (int jj = 0; jj < 16; jj++) {
            int p = lane + 32 * jj;
            float2 s = *(float2*)(row + 2 * p);
            float2 bv = __half22float2(gb[p]);
            float v0 = s.x + bv.x, v1 = s.y + bv.y;
            vals[2 * jj] = v0; vals[2 * jj + 1] = v1;
            mx = fmaxf(mx, fmaxf(v0, v1));
        }
        #pragma unroll
        for (int o = 16; o; o >>= 1) mx = fmaxf(mx, __shfl_xor_sync(0xffffffffu, mx, o));
        float sum = 0.0f;
        #pragma unroll
        for (int j = 0; j < 32; j++) {
            float e = expf(vals[j] - mx);
            vals[j] = e;
            sum += e;
        }
        #pragma unroll
        for (int o = 16; o; o >>= 1) sum += __shfl_xor_sync(0xffffffffu, sum, o);
        float inv = 1.0f / sum;
        __half2* hrow = (__half2*)row;   // fp32 scores in this row are dead now
        #pragma unroll
        for (int jj = 0; jj < 16; jj++) {
            int p = lane + 32 * jj;
            __half2 w = __floats2half2_rn(vals[2 * jj] * inv, vals[2 * jj + 1] * inv);
            hrow[p] = w;
            gb[p] = w;
        }
    }
    __syncthreads();

    // ---- Phase C: out = weights @ V; split-kt across warp halves ----
    {
        const int kg = wid >> 2;   // 0..1: even/odd kt
        const int wc = wid & 3;    // 0..3 -> 16 cols
        wmma::fragment<wmma::accumulator, 16, 16, 16, float> c[2];
        wmma::fill_fragment(c[0], 0.0f);
        wmma::fill_fragment(c[1], 0.0f);
        const __half* Vbase = gVh + (size_t)bh * SD_;
        const __half* Tbase = (const __half*)sT;
        const int tldm = TP * 2;

        uint2 pV[4];
        #pragma unroll
        for (int i = 0; i < 4; i++)
            pV[i] = *(const uint2*)(Vbase + (rowA + i * 16) * DK_ + c4);

        for (int kt = 0; kt < 16; kt++) {
            __syncthreads();
            #pragma unroll
            for (int i = 0; i < 4; i++)
                *(uint2*)&sKV[(rowA + i * 16) * 72 + c4] = pV[i];
            __syncthreads();
            if (kt < 15) {
                const int k1 = (kt + 1) * 64;
                #pragma unroll
                for (int i = 0; i < 4; i++)
                    pV[i] = *(const uint2*)(Vbase + (k1 + rowA + i * 16) * DK_ + c4);
            }
            if ((kt & 1) == kg) {
                #pragma unroll
                for (int kk = 0; kk < 4; kk++) {
                    wmma::fragment<wmma::matrix_a, 16, 16, 16, __half, wmma::row_major> a;
                    wmma::fragment<wmma::matrix_b, 16, 16, 16, __half, wmma::row_major> b;
                    wmma::load_matrix_sync(a, Tbase + kt * 64 + kk * 16, tldm);
                    wmma::load_matrix_sync(b, sKV + (kk * 16) * 72 + wc * 16, 72);
                    wmma::mma_sync(c[kk & 1], a, b, c[kk & 1]);
                }
            }
        }
        #pragma unroll
        for (int e = 0; e < c[0].num_elements; e++) c[0].x[e] += c[1].x[e];

        // FIX (R11 NaN): all warps must finish reading sT (weights) before it is
        // recycled as the fp32 reduction stage below.
        __syncthreads();

        float* red = sT;   // weights dead; reuse as 16x68 reduction stage
        if (kg == 1)
            wmma::store_matrix_sync(red + wc * 16, c[0], 68, wmma::mem_row_major);
        __syncthreads();
        if (kg == 0) {
            wmma::fragment<wmma::accumulator, 16, 16, 16, float> t;
            wmma::load_matrix_sync(t, red + wc * 16, 68, wmma::mem_row_major);
            #pragma unroll
            for (int e = 0; e < c[0].num_elements; e++) c[0].x[e] += t.x[e];
            wmma::store_matrix_sync(gO + (size_t)bh * SD_ + (size_t)q0 * DK_ + wc * 16,
                                    c[0], DK_, wmma::mem_row_major);
        }
    }
}

// ---------------------------------------------------------------------------
// Kernel 4: gO += weights[:,q,:] @ Ev[q].  fp16 MMA, fp16 weights from gS.
// ---------------------------------------------------------------------------
__global__ __launch_bounds__(256, 4)
void edgev_kernel(const float* __restrict__ Ev)
{
    __shared__ __half sA[64 * 72];
    __shared__ __half sB[64 * 72];

    const int tid = threadIdx.x;
    const int wid = tid >> 5;
    const int warpRow = wid >> 1;   // 0..3
    const int warpCol = wid & 1;    // 0..1
    const int q = blockIdx.x;
    const int rowA = tid >> 4;      // 0..15
    const int c4   = (tid & 15) * 4;

    wmma::fragment<wmma::accumulator, 16, 16, 16, float> acc[2];
    #pragma unroll
    for (int j = 0; j < 2; j++)
        wmma::load_matrix_sync(acc[j],
            gO + (size_t)(warpRow * 16) * SD_ + q * DK_ + warpCol * 32 + j * 16,
            SD_, wmma::mem_row_major);

    uint2  pA[4];
    float4 pB[4];
    #pragma unroll
    for (int i = 0; i < 4; i++) {
        int row = rowA + i * 16;
        pA[i] = *(const uint2*)(gS + (size_t)row * SS_ + (size_t)q * S_ + c4);
        pB[i] = *(const float4*)(Ev + ((size_t)q * S_ + row) * DK_ + c4);
    }

    for (int kt = 0; kt < 16; kt++) {
        __syncthreads();
        #pragma unroll
        for (int i = 0; i < 4; i++) {
            int row = rowA + i * 16;
            *(uint2*)&sA[row * 72 + c4] = pA[i];
            float4 v = pB[i];
            *(__half2*)&sB[row * 72 + c4]     = __floats2half2_rn(v.x, v.y);
            *(__half2*)&sB[row * 72 + c4 + 2] = __floats2half2_rn(v.z, v.w);
        }
        __syncthreads();
        if (kt < 15) {
            const int k1 = (kt + 1) * 64;
            #pragma unroll
            for (int i = 0; i < 4; i++) {
                int row = rowA + i * 16;
                pA[i] = *(const uint2*)(gS + (size_t)row * SS_ + (size_t)q * S_ + k1 + c4);
                pB[i] = *(const float4*)(Ev + ((size_t)q * S_ + k1 + row) * DK_ + c4);
            }
        }
        #pragma unroll
        for (int kk = 0; kk < 4; kk++) {
            wmma::fragment<wmma::matrix_a, 16, 16, 16, __half, wmma::row_major> a;
            wmma::load_matrix_sync(a, sA + (warpRow * 16) * 72 + kk * 16, 72);
            #pragma unroll
            for (int j = 0; j < 2; j++) {
                wmma::fragment<wmma::matrix_b, 16, 16, 16, __half, wmma::row_major> b;
                wmma::load_matrix_sync(b, sB + (kk * 16) * 72 + warpCol * 32 + j * 16, 72);
                wmma::mma_sync(acc[j], a, b, acc[j]);
            }
        }
    }

    #pragma unroll
    for (int j = 0; j < 2; j++)
        wmma::store_matrix_sync(
            gO + (size_t)(warpRow * 16) * SD_ + q * DK_ + warpCol * 32 + j * 16,
            acc[j], SD_, wmma::mem_row_major);
}

// ---------------------------------------------------------------------------
// Kernel 5: out = concat_heads(gO) @ Wp + bp. 3xbf16 split, tile 128x64.
// ---------------------------------------------------------------------------
__global__ __launch_bounds__(256)
void final_kernel(const float* __restrict__ Wp, const float* __restrict__ bp,
                  float* __restrict__ out)
{
    __shared__ float sBias[16 * 72];
    __shared__ __nv_bfloat16 sAhi[128 * 40], sAlo[128 * 40];
    __shared__ __nv_bfloat16 sBhi[32 * 72],  sBlo[32 * 72];

    const int tid = threadIdx.x;
    const int wid = tid >> 5;
    const int warpRow = wid >> 1;
    const int warpCol = wid & 1;
    const int m0 = blockIdx.y * 128;
    const int n0 = blockIdx.x * 64;
    const int bb = m0 >> 10;
    const int sBase = m0 & 1023;

    #pragma unroll
    for (int i = 0; i < 4; i++) {
        int idx = tid + i * 256;
        int r = idx >> 6, c = idx & 63;
        sBias[r * 72 + c] = bp[n0 + c];
    }
    __syncthreads();

    wmma::fragment<wmma::accumulator, 16, 16, 16, float> acc[2][2];
    #pragma unroll
    for (int mi = 0; mi < 2; mi++)
        #pragma unroll
        for (int ni = 0; ni < 2; ni++)
            wmma::load_matrix_sync(acc[mi][ni], sBias + warpCol * 32 + ni * 16,
                                   72, wmma::mem_row_major);

    for (int kt = 0; kt < 16; kt++) {
        const int k0 = kt * 32;
        const int h = k0 >> 6, d0 = k0 & 63;
        const float* Abase = gO + ((size_t)((bb * H_ + h) << 16)) + d0;
        #pragma unroll
        for (int i = 0; i < 4; i++) {
            int fi = tid + i * 256;
            int row = fi >> 3, c4 = (fi & 7) * 4;
            float4 v = *(const float4*)(Abase + (size_t)(sBase + row) * DK_ + c4);
            __nv_bfloat16 hx = __float2bfloat16(v.x), hy = __float2bfloat16(v.y);
            __nv_bfloat16 hz = __float2bfloat16(v.z), hw = __float2bfloat16(v.w);
            *(__nv_bfloat162*)&sAhi[row * 40 + c4]     = __nv_bfloat162(hx, hy);
            *(__nv_bfloat162*)&sAhi[row * 40 + c4 + 2] = __nv_bfloat162(hz, hw);
            *(__nv_bfloat162*)&sAlo[row * 40 + c4] =
                __nv_bfloat162(__float2bfloat16(v.x - __bfloat162float(hx)),
                               __float2bfloat16(v.y - __bfloat162float(hy)));
            *(__nv_bfloat162*)&sAlo[row * 40 + c4 + 2] =
                __nv_bfloat162(__float2bfloat16(v.z - __bfloat162float(hz)),
                               __float2bfloat16(v.w - __bfloat162float(hw)));
        }
        #pragma unroll
        for (int i = 0; i < 2; i++) {
            int fi = tid + i * 256;
            int row = fi >> 4, c4 = (fi & 15) * 4;
            float4 v = *(const float4*)(Wp + (k0 + row) * HD_ + n0 + c4);
            __nv_bfloat16 hx = __float2bfloat16(v.x), hy = __float2bfloat16(v.y);
            __nv_bfloat16 hz = __float2bfloat16(v.z), hw = __float2bfloat16(v.w);
            *(__nv_bfloat162*)&sBhi[row * 72 + c4]     = __nv_bfloat162(hx, hy);
            *(__nv_bfloat162*)&sBhi[row * 72 + c4 + 2] = __nv_bfloat162(hz, hw);
            *(__nv_bfloat162*)&sBlo[row * 72 + c4] =
                __nv_bfloat162(__float2bfloat16(v.x - __bfloat162float(hx)),
                               __float2bfloat16(v.y - __bfloat162float(hy)));
            *(__nv_bfloat162*)&sBlo[row * 72 + c4 + 2] =
                __nv_bfloat162(__float2bfloat16(v.z - __bfloat162float(hz)),
                               __float2bfloat16(v.w - __bfloat162float(hw)));
        }
        __syncthreads();
        #pragma unroll
        for (int kk = 0; kk < 2; kk++) {
            wmma::fragment<wmma::matrix_b, 16, 16, 16, __nv_bfloat16, wmma::row_major> bhf[2], blf[2];
            #pragma unroll
            for (int ni = 0; ni < 2; ni++) {
                wmma::load_matrix_sync(bhf[ni], sBhi + (kk * 16) * 72 + warpCol * 32 + ni * 16, 72);
                wmma::load_matrix_sync(blf[ni], sBlo + (kk * 16) * 72 + warpCol * 32 + ni * 16, 72);
            }
            #pragma unroll
            for (int mi = 0; mi < 2; mi++) {
                wmma::fragment<wmma::matrix_a, 16, 16, 16, __nv_bfloat16, wmma::row_major> ah, al;
                wmma::load_matrix_sync(ah, sAhi + (warpRow * 32 + mi * 16) * 40 + kk * 16, 40);
                wmma::load_matrix_sync(al, sAlo + (warpRow * 32 + mi * 16) * 40 + kk * 16, 40);
                #pragma unroll
                for (int ni = 0; ni < 2; ni++) {
                    wmma::mma_sync(acc[mi][ni], ah, bhf[ni], acc[mi][ni]);
                    wmma::mma_sync(acc[mi][ni], ah, blf[ni], acc[mi][ni]);
                    wmma::mma_sync(acc[mi][ni], al, bhf[ni], acc[mi][ni]);
                }
            }
        }
        __syncthreads();
    }

    #pragma unroll
    for (int mi = 0; mi < 2; mi++)
        #pragma unroll
        for (int ni = 0; ni < 2; ni++)
            wmma::store_matrix_sync(
                out + (size_t)(m0 + warpRow * 32 + mi * 16) * HD_ + n0 + warpCol * 32 + ni * 16,
                acc[mi][ni], HD_, wmma::mem_row_major);
}

// ---------------------------------------------------------------------------
extern "C" void kernel_launch(void* const* d_in, const int* in_sizes, int n_in,
                              void* d_out, int out_size)
{
    const float* queries = (const float*)d_in[0];
    const float* keys    = (const float*)d_in[1];
    const float* values  = (const float*)d_in[2];
    const float* Ek      = (const float*)d_in[3];
    const float* Ev      = (const float*)d_in[4];
    const float* abias   = (const float*)d_in[5];
    const float* Wq = (const float*)d_in[6];
    const float* bq = (const float*)d_in[7];
    const float* Wk = (const float*)d_in[8];
    const float* bk = (const float*)d_in[9];
    const float* Wv = (const float*)d_in[10];
    const float* bv = (const float*)d_in[11];
    const float* Wp = (const float*)d_in[12];
    const float* bp = (const float*)d_in[13];
    float* out = (float*)d_out;

    const int SMEM_PR = 128 * 68 * 4;                                   // 34816
    const int SMEM_EB = 2 * 64 * 72 * 2 + 64 * 72 * 4;                  // 36864
    const int SMEM_FA = (16 * 72 + 128 * 72) * 2 + 16 * TP * 4;         // 87040
    cudaFuncSetAttribute(fused_attn_kernel, cudaFuncAttributeMaxDynamicSharedMemorySize, SMEM_FA);

    dim3 blk(256);
    proj_kernel<<<dim3(8, 64, 3), blk, SMEM_PR>>>(queries, keys, values, Wq, Wk, Wv, bq, bk, bv);
    edge_bias_kernel<<<dim3(16, 1024), blk, SMEM_EB>>>(Ek, abias);
    fused_attn_kernel<<<dim3(64, 64), blk, SMEM_FA>>>();
    edgev_kernel<<<1024, blk>>>(Ev);
    final_kernel<<<dim3(8, 64), blk>>>(Wp, bp, out);
}

// round 13
// speedup vs baseline: 2.5524x; 1.1504x over previous
#include <cuda_runtime.h>
#include <cuda_bf16.h>
#include <cuda_fp16.h>
#include <mma.h>

using namespace nvcuda;

constexpr int B_   = 8;
constexpr int H_   = 8;
constexpr int S_   = 1024;
constexpr int DK_  = 64;
constexpr int EMB_ = 512;
constexpr int HD_  = 512;   // H*DK
constexpr int BH_  = 64;    // B*H
constexpr int SD_  = S_ * DK_;   // 65536
constexpr int SS_  = S_ * S_;    // 1048576
constexpr int THP  = 1032;       // sT row stride in halfs (2064B: 16B-aligned rows)

// Scratch (device globals: allocation-free rule)
__device__ __half gQh[BH_ * S_ * DK_];  // fp16, q pre-scaled by 1/8
__device__ __half gKh[BH_ * S_ * DK_];
__device__ __half gVh[BH_ * S_ * DK_];
__device__ float  gO[BH_ * S_ * DK_];
// gS (fp16, 128MB): score-bias before softmax; attention weights after softmax
__device__ __half gS[(size_t)BH_ * S_ * S_];

// ---------------------------------------------------------------------------
// Kernel 1: merged QKV projection, single fp16 MMA. Tile 128x64, k-chunk 64.
// ---------------------------------------------------------------------------
__global__ __launch_bounds__(256)
void proj_kernel(const float* __restrict__ Xq, const float* __restrict__ Xk,
                 const float* __restrict__ Xv,
                 const float* __restrict__ Wq, const float* __restrict__ Wk,
                 const float* __restrict__ Wv,
                 const float* __restrict__ bq, const float* __restrict__ bk,
                 const float* __restrict__ bv)
{
    extern __shared__ char psm[];
    __half* sA = (__half*)psm;               // 128 x 72
    __half* sB = sA + 128 * 72;              // 64 x 72
    float* sBias = (float*)(sB + 64 * 72);   // 16 x 72
    float* stage = (float*)psm;              // epilogue reuse: 128 x 68

    const int which = blockIdx.z;
    const float* X    = (which == 0) ? Xq : (which == 1) ? Xk : Xv;
    const float* W    = (which == 0) ? Wq : (which == 1) ? Wk : Wv;
    const float* bias = (which == 0) ? bq : (which == 1) ? bk : bv;
    __half* outp      = (which == 0) ? gQh : (which == 1) ? gKh : gVh;
    const float scale = (which == 0) ? 0.125f : 1.0f;

    const int tid = threadIdx.x;
    const int wid = tid >> 5;
    const int warpRow = wid >> 1;   // 0..3
    const int warpCol = wid & 1;    // 0..1
    const int m0 = blockIdx.y * 128;
    const int n0 = blockIdx.x * 64;
    const int bb = m0 >> 10;
    const int sBase = m0 & 1023;
    const int h  = n0 >> 6;

    #pragma unroll
    for (int i = 0; i < 4; i++) {
        int idx = tid + i * 256;
        int r = idx >> 6, c = idx & 63;
        sBias[r * 72 + c] = bias[n0 + c];
    }
    __syncthreads();

    wmma::fragment<wmma::accumulator, 16, 16, 16, float> acc[2][2];
    #pragma unroll
    for (int mi = 0; mi < 2; mi++)
        #pragma unroll
        for (int ni = 0; ni < 2; ni++)
            wmma::load_matrix_sync(acc[mi][ni], sBias + warpCol * 32 + ni * 16,
                                   72, wmma::mem_row_major);
    __syncthreads();

    for (int kt = 0; kt < 8; kt++) {
        const int k0 = kt * 64;
        #pragma unroll
        for (int i = 0; i < 8; i++) {
            int fi = tid + i * 256;
            int row = fi >> 4, c4 = (fi & 15) * 4;
            float4 v = *(const float4*)(X + (m0 + row) * EMB_ + k0 + c4);
            *(__half2*)&sA[row * 72 + c4]     = __floats2half2_rn(v.x, v.y);
            *(__half2*)&sA[row * 72 + c4 + 2] = __floats2half2_rn(v.z, v.w);
        }
        #pragma unroll
        for (int i = 0; i < 4; i++) {
            int fi = tid + i * 256;
            int row = fi >> 4, c4 = (fi & 15) * 4;
            float4 v = *(const float4*)(W + (k0 + row) * HD_ + n0 + c4);
            *(__half2*)&sB[row * 72 + c4]     = __floats2half2_rn(v.x, v.y);
            *(__half2*)&sB[row * 72 + c4 + 2] = __floats2half2_rn(v.z, v.w);
        }
        __syncthreads();
        #pragma unroll
        for (int kk = 0; kk < 4; kk++) {
            wmma::fragment<wmma::matrix_b, 16, 16, 16, __half, wmma::row_major> bf[2];
            #pragma unroll
            for (int ni = 0; ni < 2; ni++)
                wmma::load_matrix_sync(bf[ni], sB + (kk * 16) * 72 + warpCol * 32 + ni * 16, 72);
            #pragma unroll
            for (int mi = 0; mi < 2; mi++) {
                wmma::fragment<wmma::matrix_a, 16, 16, 16, __half, wmma::row_major> a;
                wmma::load_matrix_sync(a, sA + (warpRow * 32 + mi * 16) * 72 + kk * 16, 72);
                #pragma unroll
                for (int ni = 0; ni < 2; ni++)
                    wmma::mma_sync(acc[mi][ni], a, bf[ni], acc[mi][ni]);
            }
        }
        __syncthreads();
    }

    // Epilogue: scale, stage fp32, write fp16
    #pragma unroll
    for (int mi = 0; mi < 2; mi++)
        #pragma unroll
        for (int ni = 0; ni < 2; ni++) {
            #pragma unroll
            for (int e = 0; e < acc[mi][ni].num_elements; e++)
                acc[mi][ni].x[e] *= scale;
            wmma::store_matrix_sync(stage + (warpRow * 32 + mi * 16) * 68 + warpCol * 32 + ni * 16,
                                    acc[mi][ni], 68, wmma::mem_row_major);
        }
    __syncthreads();
    __half* obase = outp + ((size_t)((bb * H_ + h) << 16));
    #pragma unroll
    for (int i = 0; i < 16; i++) {
        int idx = tid + i * 256;
        int r = idx >> 5, cp = (idx & 31) * 2;
        float2 v = *(float2*)(stage + r * 68 + cp);
        *(__half2*)(obase + (size_t)(sBase + r) * DK_ + cp) = __floats2half2_rn(v.x, v.y);
    }
}

// ---------------------------------------------------------------------------
// Kernel 2: gS[bh,q,n] = gQh[bh,q,:]·Ek[q,n,:] + abias[b,q,n]. fp16 MMA,
// fp16 output to gS.
// ---------------------------------------------------------------------------
__global__ __launch_bounds__(256, 4)
void edge_bias_kernel(const float* __restrict__ Ek, const float* __restrict__ abias)
{
    extern __shared__ char esm[];
    __half* sA  = (__half*)esm;              // 64 x 72 (row=bh, col=d)
    __half* sEk = sA + 64 * 72;              // 64 x 72 (row=n, col=d)
    float* sBias = (float*)(sEk + 64 * 72);  // 64 x 72 (bias; reused as stage)

    const int tid = threadIdx.x;
    const int wid = tid >> 5;
    const int wr  = wid >> 2;            // 0..1
    const int wc  = wid & 3;             // 0..3 -> 16 cols
    const int q   = blockIdx.y;
    const int n0  = blockIdx.x * 64;
    const int rowA = tid >> 4;           // 0..15
    const int c4   = (tid & 15) * 4;

    #pragma unroll
    for (int i = 0; i < 4; i++) {
        int row = rowA + i * 16;
        *(uint2*)&sA[row * 72 + c4] =
            *(const uint2*)(gQh + (size_t)row * SD_ + q * DK_ + c4);
        float4 v = *(const float4*)(Ek + ((size_t)q * S_ + n0 + row) * DK_ + c4);
        *(__half2*)&sEk[row * 72 + c4]     = __floats2half2_rn(v.x, v.y);
        *(__half2*)&sEk[row * 72 + c4 + 2] = __floats2half2_rn(v.z, v.w);
    }
    #pragma unroll
    for (int i = 0; i < 16; i++) {
        int idx = tid + i * 256;
        int r = idx >> 6, c = idx & 63;
        sBias[r * 72 + c] = abias[(size_t)(r >> 3) * SS_ + (size_t)q * S_ + n0 + c];
    }
    __syncthreads();

    wmma::fragment<wmma::accumulator, 16, 16, 16, float> acc[2];
    #pragma unroll
    for (int mi = 0; mi < 2; mi++)
        wmma::load_matrix_sync(acc[mi], sBias + (wr * 32 + mi * 16) * 72 + wc * 16,
                               72, wmma::mem_row_major);

    #pragma unroll
    for (int kk = 0; kk < 4; kk++) {
        wmma::fragment<wmma::matrix_b, 16, 16, 16, __half, wmma::col_major> b;
        wmma::load_matrix_sync(b, sEk + (wc * 16) * 72 + kk * 16, 72);
        #pragma unroll
        for (int mi = 0; mi < 2; mi++) {
            wmma::fragment<wmma::matrix_a, 16, 16, 16, __half, wmma::row_major> a;
            wmma::load_matrix_sync(a, sA + (wr * 32 + mi * 16) * 72 + kk * 16, 72);
            wmma::mma_sync(acc[mi], a, b, acc[mi]);
        }
    }

    __syncthreads();   // all warps done reading sBias for acc init
    #pragma unroll
    for (int mi = 0; mi < 2; mi++)
        wmma::store_matrix_sync(sBias + (wr * 32 + mi * 16) * 72 + wc * 16,
                                acc[mi], 72, wmma::mem_row_major);
    __syncthreads();
    #pragma unroll
    for (int i = 0; i < 8; i++) {
        int idx = tid + i * 256;
        int r = idx >> 5, u = idx & 31;
        float2 f = *(float2*)(sBias + r * 72 + 2 * u);
        ((__half2*)(gS + (size_t)r * SS_ + (size_t)q * S_ + n0))[u] =
            __floats2half2_rn(f.x, f.y);
    }
}

// ---------------------------------------------------------------------------
// Kernel 3 (FUSED): 16 q-rows/CTA, ~4 CTAs/SM (53.8KB smem). fp16 QK^T with
// fp16 accumulator -> fp16 scores in sT -> 3-pass softmax -> fp16 weights in
// sT + gS -> fp16 W @ V (128-k chunks) -> gO.
// ---------------------------------------------------------------------------
__global__ __launch_bounds__(256, 4)
void fused_attn_kernel()
{
    extern __shared__ char fsm[];
    __half* sQ  = (__half*)fsm;              // 16 x 72
    __half* sKV = sQ + 16 * 72;              // 128 x 72
    __half* sT  = sKV + 128 * 72;            // 16 x THP (fp16 scores/weights)

    const int tid = threadIdx.x;
    const int wid = tid >> 5;
    const int lane = tid & 31;
    const int bh = blockIdx.y;
    const int q0 = blockIdx.x * 16;
    const int rowA = tid >> 4;               // 0..15
    const int c4   = (tid & 15) * 4;         // half-index

    {
        int row = tid >> 4, cc = (tid & 15) * 4;
        *(uint2*)&sQ[row * 72 + cc] =
            *(const uint2*)(gQh + (size_t)bh * SD_ + (q0 + row) * DK_ + cc);
    }
    __syncthreads();

    // ---- Phase A: raw scores, fp16 MMA with fp16 accumulator ----
    {
        wmma::fragment<wmma::matrix_a, 16, 16, 16, __half, wmma::row_major> a[4];
        #pragma unroll
        for (int kk = 0; kk < 4; kk++)
            wmma::load_matrix_sync(a[kk], sQ + kk * 16, 72);

        const __half* Kbase = gKh + (size_t)bh * SD_;
        uint2 pK[8];
        #pragma unroll
        for (int i = 0; i < 8; i++)
            pK[i] = *(const uint2*)(Kbase + (rowA + i * 16) * DK_ + c4);

        for (int nc = 0; nc < 8; nc++) {
            __syncthreads();
            #pragma unroll
            for (int i = 0; i < 8; i++)
                *(uint2*)&sKV[(rowA + i * 16) * 72 + c4] = pK[i];
            __syncthreads();
            if (nc < 7) {
                const int n1 = (nc + 1) * 128;
                #pragma unroll
                for (int i = 0; i < 8; i++)
                    pK[i] = *(const uint2*)(Kbase + (n1 + rowA + i * 16) * DK_ + c4);
            }
            const int ncol = wid * 16;
            wmma::fragment<wmma::accumulator, 16, 16, 16, __half> acc;
            wmma::fill_fragment(acc, __float2half(0.0f));
            #pragma unroll
            for (int kk = 0; kk < 4; kk++) {
                wmma::fragment<wmma::matrix_b, 16, 16, 16, __half, wmma::col_major> b;
                wmma::load_matrix_sync(b, sKV + ncol * 72 + kk * 16, 72);
                wmma::mma_sync(acc, a[kk], b, acc);
            }
            wmma::store_matrix_sync(sT + nc * 128 + ncol, acc, THP, wmma::mem_row_major);
        }
    }
    __syncthreads();

    // ---- Phase B: 3-pass softmax over fp16 scores + fp16 bias ----
    #pragma unroll
    for (int rr = 0; rr < 2; rr++) {
        int r = wid * 2 + rr;
        __half2* row2 = (__half2*)(sT + r * THP);
        __half2* gb = (__half2*)(gS + ((size_t)bh * S_ + q0 + r) * S_);
        // pass 1: max
        float mx = -3.0e38f;
        #pragma unroll
        for (int jj = 0; jj < 16; jj++) {
            int p = lane + 32 * jj;
            float2 s = __half22float2(row2[p]);
            float2 bv = __half22float2(gb[p]);
            mx = fmaxf(mx, fmaxf(s.x + bv.x, s.y + bv.y));
        }
        #pragma unroll
        for (int o = 16; o; o >>= 1) mx = fmaxf(mx, __shfl_xor_sync(0xffffffffu, mx, o));
        // pass 2: exp + sum (store exp back into row)
        float sum = 0.0f;
        #pragma unroll
        for (int jj = 0; jj < 16; jj++) {
            int p = lane + 32 * jj;
            float2 s = __half22float2(row2[p]);
            float2 bv = __half22float2(gb[p]);
            float e0 = expf(s.x + bv.x - mx);
            float e1 = expf(s.y + bv.y - mx);
            row2[p] = __floats2half2_rn(e0, e1);
            sum += e0 + e1;
        }
        #pragma unroll
        for (int o = 16; o; o >>= 1) sum += __shfl_xor_sync(0xffffffffu, sum, o);
        float inv = 1.0f / sum;
        // pass 3: normalize -> sT + gS
        #pragma unroll
        for (int jj = 0; jj < 16; jj++) {
            int p = lane + 32 * jj;
            float2 e = __half22float2(row2[p]);
            __half2 w = __floats2half2_rn(e.x * inv, e.y * inv);
            row2[p] = w;
            gb[p] = w;
        }
    }
    __syncthreads();

    // ---- Phase C: out = weights @ V; 128-k chunks, split-kk across warp halves ----
    {
        const int kg = wid >> 2;   // 0..1: kk 0-3 vs 4-7
        const int wc = wid & 3;    // 0..3 -> 16 cols
        wmma::fragment<wmma::accumulator, 16, 16, 16, float> c[2];
        wmma::fill_fragment(c[0], 0.0f);
        wmma::fill_fragment(c[1], 0.0f);
        const __half* Vbase = gVh + (size_t)bh * SD_;

        uint2 pV[8];
        #pragma unroll
        for (int i = 0; i < 8; i++)
            pV[i] = *(const uint2*)(Vbase + (rowA + i * 16) * DK_ + c4);

        for (int kt = 0; kt < 8; kt++) {
            __syncthreads();
            #pragma unroll
            for (int i = 0; i < 8; i++)
                *(uint2*)&sKV[(rowA + i * 16) * 72 + c4] = pV[i];
            __syncthreads();
            if (kt < 7) {
                const int k1 = (kt + 1) * 128;
                #pragma unroll
                for (int i = 0; i < 8; i++)
                    pV[i] = *(const uint2*)(Vbase + (k1 + rowA + i * 16) * DK_ + c4);
            }
            #pragma unroll
            for (int kx = 0; kx < 4; kx++) {
                const int kk = kg * 4 + kx;
                wmma::fragment<wmma::matrix_a, 16, 16, 16, __half, wmma::row_major> a;
                wmma::fragment<wmma::matrix_b, 16, 16, 16, __half, wmma::row_major> b;
                wmma::load_matrix_sync(a, sT + kt * 128 + kk * 16, THP);
                wmma::load_matrix_sync(b, sKV + (kk * 16) * 72 + wc * 16, 72);
                wmma::mma_sync(c[kx & 1], a, b, c[kx & 1]);
            }
        }
        #pragma unroll
        for (int e = 0; e < c[0].num_elements; e++) c[0].x[e] += c[1].x[e];

        // all warps must finish reading sT (weights) before recycling it
        __syncthreads();

        float* red = (float*)sT;   // weights dead; reuse as 16x68 fp32 stage
        if (kg == 1)
            wmma::store_matrix_sync(red + wc * 16, c[0], 68, wmma::mem_row_major);
        __syncthreads();
        if (kg == 0) {
            wmma::fragment<wmma::accumulator, 16, 16, 16, float> t;
            wmma::load_matrix_sync(t, red + wc * 16, 68, wmma::mem_row_major);
            #pragma unroll
            for (int e = 0; e < c[0].num_elements; e++) c[0].x[e] += t.x[e];
            wmma::store_matrix_sync(gO + (size_t)bh * SD_ + (size_t)q0 * DK_ + wc * 16,
                                    c[0], DK_, wmma::mem_row_major);
        }
    }
}

// ---------------------------------------------------------------------------
// Kernel 4: gO += weights[:,q,:] @ Ev[q].  fp16 MMA, fp16 weights from gS.
// ---------------------------------------------------------------------------
__global__ __launch_bounds__(256, 4)
void edgev_kernel(const float* __restrict__ Ev)
{
    __shared__ __half sA[64 * 72];
    __shared__ __half sB[64 * 72];

    const int tid = threadIdx.x;
    const int wid = tid >> 5;
    const int warpRow = wid >> 1;   // 0..3
    const int warpCol = wid & 1;    // 0..1
    const int q = blockIdx.x;
    const int rowA = tid >> 4;      // 0..15
    const int c4   = (tid & 15) * 4;

    wmma::fragment<wmma::accumulator, 16, 16, 16, float> acc[2];
    #pragma unroll
    for (int j = 0; j < 2; j++)
        wmma::load_matrix_sync(acc[j],
            gO + (size_t)(warpRow * 16) * SD_ + q * DK_ + warpCol * 32 + j * 16,
            SD_, wmma::mem_row_major);

    uint2  pA[4];
    float4 pB[4];
    #pragma unroll
    for (int i = 0; i < 4; i++) {
        int row = rowA + i * 16;
        pA[i] = *(const uint2*)(gS + (size_t)row * SS_ + (size_t)q * S_ + c4);
        pB[i] = *(const float4*)(Ev + ((size_t)q * S_ + row) * DK_ + c4);
    }

    for (int kt = 0; kt < 16; kt++) {
        __syncthreads();
        #pragma unroll
        for (int i = 0; i < 4; i++) {
            int row = rowA + i * 16;
            *(uint2*)&sA[row * 72 + c4] = pA[i];
            float4 v = pB[i];
            *(__half2*)&sB[row * 72 + c4]     = __floats2half2_rn(v.x, v.y);
            *(__half2*)&sB[row * 72 + c4 + 2] = __floats2half2_rn(v.z, v.w);
        }
        __syncthreads();
        if (kt < 15) {
            const int k1 = (kt + 1) * 64;
            #pragma unroll
            for (int i = 0; i < 4; i++) {
                int row = rowA + i * 16;
                pA[i] = *(const uint2*)(gS + (size_t)row * SS_ + (size_t)q * S_ + k1 + c4);
                pB[i] = *(const float4*)(Ev + ((size_t)q * S_ + k1 + row) * DK_ + c4);
            }
        }
        #pragma unroll
        for (int kk = 0; kk < 4; kk++) {
            wmma::fragment<wmma::matrix_a, 16, 16, 16, __half, wmma::row_major> a;
            wmma::load_matrix_sync(a, sA + (warpRow * 16) * 72 + kk * 16, 72);
            #pragma unroll
            for (int j = 0; j < 2; j++) {
                wmma::fragment<wmma::matrix_b, 16, 16, 16, __half, wmma::row_major> b;
                wmma::load_matrix_sync(b, sB + (kk * 16) * 72 + warpCol * 32 + j * 16, 72);
                wmma::mma_sync(acc[j], a, b, acc[j]);
            }
        }
    }

    #pragma unroll
    for (int j = 0; j < 2; j++)
        wmma::store_matrix_sync(
            gO + (size_t)(warpRow * 16) * SD_ + q * DK_ + warpCol * 32 + j * 16,
            acc[j], SD_, wmma::mem_row_major);
}

// ---------------------------------------------------------------------------
// Kernel 5: out = concat_heads(gO) @ Wp + bp. 3xbf16 split, tile 128x64.
// ---------------------------------------------------------------------------
__global__ __launch_bounds__(256)
void final_kernel(const float* __restrict__ Wp, const float* __restrict__ bp,
                  float* __restrict__ out)
{
    __shared__ float sBias[16 * 72];
    __shared__ __nv_bfloat16 sAhi[128 * 40], sAlo[128 * 40];
    __shared__ __nv_bfloat16 sBhi[32 * 72],  sBlo[32 * 72];

    const int tid = threadIdx.x;
    const int wid = tid >> 5;
    const int warpRow = wid >> 1;
    const int warpCol = wid & 1;
    const int m0 = blockIdx.y * 128;
    const int n0 = blockIdx.x * 64;
    const int bb = m0 >> 10;
    const int sBase = m0 & 1023;

    #pragma unroll
    for (int i = 0; i < 4; i++) {
        int idx = tid + i * 256;
        int r = idx >> 6, c = idx & 63;
        sBias[r * 72 + c] = bp[n0 + c];
    }
    __syncthreads();

    wmma::fragment<wmma::accumulator, 16, 16, 16, float> acc[2][2];
    #pragma unroll
    for (int mi = 0; mi < 2; mi++)
        #pragma unroll
        for (int ni = 0; ni < 2; ni++)
            wmma::load_matrix_sync(acc[mi][ni], sBias + warpCol * 32 + ni * 16,
                                   72, wmma::mem_row_major);

    for (int kt = 0; kt < 16; kt++) {
        const int k0 = kt * 32;
        const int h = k0 >> 6, d0 = k0 & 63;
        const float* Abase = gO + ((size_t)((bb * H_ + h) << 16)) + d0;
        #pragma unroll
        for (int i = 0; i < 4; i++) {
            int fi = tid + i * 256;
            int row = fi >> 3, c4 = (fi & 7) * 4;
            float4 v = *(const float4*)(Abase + (size_t)(sBase + row) * DK_ + c4);
            __nv_bfloat16 hx = __float2bfloat16(v.x), hy = __float2bfloat16(v.y);
            __nv_bfloat16 hz = __float2bfloat16(v.z), hw = __float2bfloat16(v.w);
            *(__nv_bfloat162*)&sAhi[row * 40 + c4]     = __nv_bfloat162(hx, hy);
            *(__nv_bfloat162*)&sAhi[row * 40 + c4 + 2] = __nv_bfloat162(hz, hw);
            *(__nv_bfloat162*)&sAlo[row * 40 + c4] =
                __nv_bfloat162(__float2bfloat16(v.x - __bfloat162float(hx)),
                               __float2bfloat16(v.y - __bfloat162float(hy)));
            *(__nv_bfloat162*)&sAlo[row * 40 + c4 + 2] =
                __nv_bfloat162(__float2bfloat16(v.z - __bfloat162float(hz)),
                               __float2bfloat16(v.w - __bfloat162float(hw)));
        }
        #pragma unroll
        for (int i = 0; i < 2; i++) {
            int fi = tid + i * 256;
            int row = fi >> 4, c4 = (fi & 15) * 4;
            float4 v = *(const float4*)(Wp + (k0 + row) * HD_ + n0 + c4);
            __nv_bfloat16 hx = __float2bfloat16(v.x), hy = __float2bfloat16(v.y);
            __nv_bfloat16 hz = __float2bfloat16(v.z), hw = __float2bfloat16(v.w);
            *(__nv_bfloat162*)&sBhi[row * 72 + c4]     = __nv_bfloat162(hx, hy);
            *(__nv_bfloat162*)&sBhi[row * 72 + c4 + 2] = __nv_bfloat162(hz, hw);
            *(__nv_bfloat162*)&sBlo[row * 72 + c4] =
                __nv_bfloat162(__float2bfloat16(v.x - __bfloat162float(hx)),
                               __float2bfloat16(v.y - __bfloat162float(hy)));
            *(__nv_bfloat162*)&sBlo[row * 72 + c4 + 2] =
                __nv_bfloat162(__float2bfloat16(v.z - __bfloat162float(hz)),
                               __float2bfloat16(v.w - __bfloat162float(hw)));
        }
        __syncthreads();
        #pragma unroll
        for (int kk = 0; kk < 2; kk++) {
            wmma::fragment<wmma::matrix_b, 16, 16, 16, __nv_bfloat16, wmma::row_major> bhf[2], blf[2];
            #pragma unroll
            for (int ni = 0; ni < 2; ni++) {
                wmma::load_matrix_sync(bhf[ni], sBhi + (kk * 16) * 72 + warpCol * 32 + ni * 16, 72);
                wmma::load_matrix_sync(blf[ni], sBlo + (kk * 16) * 72 + warpCol * 32 + ni * 16, 72);
            }
            #pragma unroll
            for (int mi = 0; mi < 2; mi++) {
                wmma::fragment<wmma::matrix_a, 16, 16, 16, __nv_bfloat16, wmma::row_major> ah, al;
                wmma::load_matrix_sync(ah, sAhi + (warpRow * 32 + mi * 16) * 40 + kk * 16, 40);
                wmma::load_matrix_sync(al, sAlo + (warpRow * 32 + mi * 16) * 40 + kk * 16, 40);
                #pragma unroll
                for (int ni = 0; ni < 2; ni++) {
                    wmma::mma_sync(acc[mi][ni], ah, bhf[ni], acc[mi][ni]);
                    wmma::mma_sync(acc[mi][ni], ah, blf[ni], acc[mi][ni]);
                    wmma::mma_sync(acc[mi][ni], al, bhf[ni], acc[mi][ni]);
                }
            }
        }
        __syncthreads();
    }

    #pragma unroll
    for (int mi = 0; mi < 2; mi++)
        #pragma unroll
        for (int ni = 0; ni < 2; ni++)
            wmma::store_matrix_sync(
                out + (size_t)(m0 + warpRow * 32 + mi * 16) * HD_ + n0 + warpCol * 32 + ni * 16,
                acc[mi][ni], HD_, wmma::mem_row_major);
}

// ---------------------------------------------------------------------------
extern "C" void kernel_launch(void* const* d_in, const int* in_sizes, int n_in,
                              void* d_out, int out_size)
{
    const float* queries = (const float*)d_in[0];
    const float* keys    = (const float*)d_in[1];
    const float* values  = (const float*)d_in[2];
    const float* Ek      = (const float*)d_in[3];
    const float* Ev      = (const float*)d_in[4];
    const float* abias   = (const float*)d_in[5];
    const float* Wq = (const float*)d_in[6];
    const float* bq = (const float*)d_in[7];
    const float* Wk = (const float*)d_in[8];
    const float* bk = (const float*)d_in[9];
    const float* Wv = (const float*)d_in[10];
    const float* bv = (const float*)d_in[11];
    const float* Wp = (const float*)d_in[12];
    const float* bp = (const float*)d_in[13];
    float* out = (float*)d_out;

    const int SMEM_PR = 128 * 68 * 4;                                   // 34816
    const int SMEM_EB = 2 * 64 * 72 * 2 + 64 * 72 * 4;                  // 36864
    const int SMEM_FA = (16 * 72 + 128 * 72) * 2 + 16 * THP * 2;        // 53760
    cudaFuncSetAttribute(fused_attn_kernel, cudaFuncAttributeMaxDynamicSharedMemorySize, SMEM_FA);

    dim3 blk(256);
    proj_kernel<<<dim3(8, 64, 3), blk, SMEM_PR>>>(queries, keys, values, Wq, Wk, Wv, bq, bk, bv);
    edge_bias_kernel<<<dim3(16, 1024), blk, SMEM_EB>>>(Ek, abias);
    fused_attn_kernel<<<dim3(64, 64), blk, SMEM_FA>>>();
    edgev_kernel<<<1024, blk>>>(Ev);
    final_kernel<<<dim3(8, 64), blk>>>(Wp, bp, out);
}

// round 14
// speedup vs baseline: 2.7582x; 1.0806x over previous
#include <cuda_runtime.h>
#include <cuda_bf16.h>
#include <cuda_fp16.h>
#include <mma.h>

using namespace nvcuda;

constexpr int B_   = 8;
constexpr int H_   = 8;
constexpr int S_   = 1024;
constexpr int DK_  = 64;
constexpr int EMB_ = 512;
constexpr int HD_  = 512;   // H*DK
constexpr int BH_  = 64;    // B*H
constexpr int SD_  = S_ * DK_;   // 65536
constexpr int SS_  = S_ * S_;    // 1048576
constexpr int THP  = 1032;       // sT row stride in halfs (2064B: 16B-aligned rows)

// Scratch (device globals: allocation-free rule)
__device__ __half gQh[BH_ * S_ * DK_];  // fp16, q pre-scaled by 1/8
__device__ __half gKh[BH_ * S_ * DK_];
__device__ __half gVh[BH_ * S_ * DK_];
__device__ float  gO[BH_ * S_ * DK_];
// gS (fp16, 128MB): score-bias before softmax; attention weights after softmax
__device__ __half gS[(size_t)BH_ * S_ * S_];

// ---------------------------------------------------------------------------
// Kernel 1: merged QKV projection, single fp16 MMA. Tile 128x64, k-chunk 64.
// Register-prefetch pipelined.
// ---------------------------------------------------------------------------
__global__ __launch_bounds__(256, 2)
void proj_kernel(const float* __restrict__ Xq, const float* __restrict__ Xk,
                 const float* __restrict__ Xv,
                 const float* __restrict__ Wq, const float* __restrict__ Wk,
                 const float* __restrict__ Wv,
                 const float* __restrict__ bq, const float* __restrict__ bk,
                 const float* __restrict__ bv)
{
    extern __shared__ char psm[];
    __half* sA = (__half*)psm;               // 128 x 72
    __half* sB = sA + 128 * 72;              // 64 x 72
    float* sBias = (float*)(sB + 64 * 72);   // 16 x 72
    float* stage = (float*)psm;              // epilogue reuse: 128 x 68

    const int which = blockIdx.z;
    const float* X    = (which == 0) ? Xq : (which == 1) ? Xk : Xv;
    const float* W    = (which == 0) ? Wq : (which == 1) ? Wk : Wv;
    const float* bias = (which == 0) ? bq : (which == 1) ? bk : bv;
    __half* outp      = (which == 0) ? gQh : (which == 1) ? gKh : gVh;
    const float scale = (which == 0) ? 0.125f : 1.0f;

    const int tid = threadIdx.x;
    const int wid = tid >> 5;
    const int warpRow = wid >> 1;   // 0..3
    const int warpCol = wid & 1;    // 0..1
    const int m0 = blockIdx.y * 128;
    const int n0 = blockIdx.x * 64;
    const int bb = m0 >> 10;
    const int sBase = m0 & 1023;
    const int h  = n0 >> 6;
    const int rowA = tid >> 4;      // 0..15
    const int c4   = (tid & 15) * 4;

    #pragma unroll
    for (int i = 0; i < 4; i++) {
        int idx = tid + i * 256;
        int r = idx >> 6, c = idx & 63;
        sBias[r * 72 + c] = bias[n0 + c];
    }
    __syncthreads();

    wmma::fragment<wmma::accumulator, 16, 16, 16, float> acc[2][2];
    #pragma unroll
    for (int mi = 0; mi < 2; mi++)
        #pragma unroll
        for (int ni = 0; ni < 2; ni++)
            wmma::load_matrix_sync(acc[mi][ni], sBias + warpCol * 32 + ni * 16,
                                   72, wmma::mem_row_major);

    // prefetch chunk 0
    float4 pA[8], pW[4];
    #pragma unroll
    for (int i = 0; i < 8; i++)
        pA[i] = *(const float4*)(X + (m0 + rowA + i * 16) * EMB_ + c4);
    #pragma unroll
    for (int i = 0; i < 4; i++)
        pW[i] = *(const float4*)(W + (rowA + i * 16) * HD_ + n0 + c4);

    for (int kt = 0; kt < 8; kt++) {
        __syncthreads();
        #pragma unroll
        for (int i = 0; i < 8; i++) {
            int row = rowA + i * 16;
            *(__half2*)&sA[row * 72 + c4]     = __floats2half2_rn(pA[i].x, pA[i].y);
            *(__half2*)&sA[row * 72 + c4 + 2] = __floats2half2_rn(pA[i].z, pA[i].w);
        }
        #pragma unroll
        for (int i = 0; i < 4; i++) {
            int row = rowA + i * 16;
            *(__half2*)&sB[row * 72 + c4]     = __floats2half2_rn(pW[i].x, pW[i].y);
            *(__half2*)&sB[row * 72 + c4 + 2] = __floats2half2_rn(pW[i].z, pW[i].w);
        }
        __syncthreads();
        if (kt < 7) {
            const int k1 = (kt + 1) * 64;
            #pragma unroll
            for (int i = 0; i < 8; i++)
                pA[i] = *(const float4*)(X + (m0 + rowA + i * 16) * EMB_ + k1 + c4);
            #pragma unroll
            for (int i = 0; i < 4; i++)
                pW[i] = *(const float4*)(W + (k1 + rowA + i * 16) * HD_ + n0 + c4);
        }
        #pragma unroll
        for (int kk = 0; kk < 4; kk++) {
            wmma::fragment<wmma::matrix_b, 16, 16, 16, __half, wmma::row_major> bf[2];
            #pragma unroll
            for (int ni = 0; ni < 2; ni++)
                wmma::load_matrix_sync(bf[ni], sB + (kk * 16) * 72 + warpCol * 32 + ni * 16, 72);
            #pragma unroll
            for (int mi = 0; mi < 2; mi++) {
                wmma::fragment<wmma::matrix_a, 16, 16, 16, __half, wmma::row_major> a;
                wmma::load_matrix_sync(a, sA + (warpRow * 32 + mi * 16) * 72 + kk * 16, 72);
                #pragma unroll
                for (int ni = 0; ni < 2; ni++)
                    wmma::mma_sync(acc[mi][ni], a, bf[ni], acc[mi][ni]);
            }
        }
    }
    __syncthreads();

    // Epilogue: scale, stage fp32, write fp16
    #pragma unroll
    for (int mi = 0; mi < 2; mi++)
        #pragma unroll
        for (int ni = 0; ni < 2; ni++) {
            #pragma unroll
            for (int e = 0; e < acc[mi][ni].num_elements; e++)
                acc[mi][ni].x[e] *= scale;
            wmma::store_matrix_sync(stage + (warpRow * 32 + mi * 16) * 68 + warpCol * 32 + ni * 16,
                                    acc[mi][ni], 68, wmma::mem_row_major);
        }
    __syncthreads();
    __half* obase = outp + ((size_t)((bb * H_ + h) << 16));
    #pragma unroll
    for (int i = 0; i < 16; i++) {
        int idx = tid + i * 256;
        int r = idx >> 5, cp = (idx & 31) * 2;
        float2 v = *(float2*)(stage + r * 68 + cp);
        *(__half2*)(obase + (size_t)(sBase + r) * DK_ + cp) = __floats2half2_rn(v.x, v.y);
    }
}

// ---------------------------------------------------------------------------
// Kernel 2: gS[bh,q,n] = gQh[bh,q,:]·Ek[q,n,:] + abias[b,q,n]. fp16 MMA,
// fp16 output to gS.
// ---------------------------------------------------------------------------
__global__ __launch_bounds__(256, 4)
void edge_bias_kernel(const float* __restrict__ Ek, const float* __restrict__ abias)
{
    extern __shared__ char esm[];
    __half* sA  = (__half*)esm;              // 64 x 72 (row=bh, col=d)
    __half* sEk = sA + 64 * 72;              // 64 x 72 (row=n, col=d)
    float* sBias = (float*)(sEk + 64 * 72);  // 64 x 72 (bias; reused as stage)

    const int tid = threadIdx.x;
    const int wid = tid >> 5;
    const int wr  = wid >> 2;            // 0..1
    const int wc  = wid & 3;             // 0..3 -> 16 cols
    const int q   = blockIdx.y;
    const int n0  = blockIdx.x * 64;
    const int rowA = tid >> 4;           // 0..15
    const int c4   = (tid & 15) * 4;

    #pragma unroll
    for (int i = 0; i < 4; i++) {
        int row = rowA + i * 16;
        *(uint2*)&sA[row * 72 + c4] =
            *(const uint2*)(gQh + (size_t)row * SD_ + q * DK_ + c4);
        float4 v = *(const float4*)(Ek + ((size_t)q * S_ + n0 + row) * DK_ + c4);
        *(__half2*)&sEk[row * 72 + c4]     = __floats2half2_rn(v.x, v.y);
        *(__half2*)&sEk[row * 72 + c4 + 2] = __floats2half2_rn(v.z, v.w);
    }
    #pragma unroll
    for (int i = 0; i < 16; i++) {
        int idx = tid + i * 256;
        int r = idx >> 6, c = idx & 63;
        sBias[r * 72 + c] = abias[(size_t)(r >> 3) * SS_ + (size_t)q * S_ + n0 + c];
    }
    __syncthreads();

    wmma::fragment<wmma::accumulator, 16, 16, 16, float> acc[2];
    #pragma unroll
    for (int mi = 0; mi < 2; mi++)
        wmma::load_matrix_sync(acc[mi], sBias + (wr * 32 + mi * 16) * 72 + wc * 16,
                               72, wmma::mem_row_major);

    #pragma unroll
    for (int kk = 0; kk < 4; kk++) {
        wmma::fragment<wmma::matrix_b, 16, 16, 16, __half, wmma::col_major> b;
        wmma::load_matrix_sync(b, sEk + (wc * 16) * 72 + kk * 16, 72);
        #pragma unroll
        for (int mi = 0; mi < 2; mi++) {
            wmma::fragment<wmma::matrix_a, 16, 16, 16, __half, wmma::row_major> a;
            wmma::load_matrix_sync(a, sA + (wr * 32 + mi * 16) * 72 + kk * 16, 72);
            wmma::mma_sync(acc[mi], a, b, acc[mi]);
        }
    }

    __syncthreads();   // all warps done reading sBias for acc init
    #pragma unroll
    for (int mi = 0; mi < 2; mi++)
        wmma::store_matrix_sync(sBias + (wr * 32 + mi * 16) * 72 + wc * 16,
                                acc[mi], 72, wmma::mem_row_major);
    __syncthreads();
    #pragma unroll
    for (int i = 0; i < 8; i++) {
        int idx = tid + i * 256;
        int r = idx >> 5, u = idx & 31;
        float2 f = *(float2*)(sBias + r * 72 + 2 * u);
        ((__half2*)(gS + (size_t)r * SS_ + (size_t)q * S_ + n0))[u] =
            __floats2half2_rn(f.x, f.y);
    }
}

// ---------------------------------------------------------------------------
// Kernel 3 (FUSED): 16 q-rows/CTA, 4 CTAs/SM. fp16 QK^T (fp16 acc) -> fp16
// scores in sT -> 3-pass softmax -> fp16 weights in sT + gS -> fp16 W @ V.
// ---------------------------------------------------------------------------
__global__ __launch_bounds__(256, 4)
void fused_attn_kernel()
{
    extern __shared__ char fsm[];
    __half* sQ  = (__half*)fsm;              // 16 x 72
    __half* sKV = sQ + 16 * 72;              // 128 x 72
    __half* sT  = sKV + 128 * 72;            // 16 x THP (fp16 scores/weights)

    const int tid = threadIdx.x;
    const int wid = tid >> 5;
    const int lane = tid & 31;
    const int bh = blockIdx.y;
    const int q0 = blockIdx.x * 16;
    const int rowA = tid >> 4;               // 0..15
    const int c4   = (tid & 15) * 4;         // half-index

    {
        int row = tid >> 4, cc = (tid & 15) * 4;
        *(uint2*)&sQ[row * 72 + cc] =
            *(const uint2*)(gQh + (size_t)bh * SD_ + (q0 + row) * DK_ + cc);
    }
    __syncthreads();

    // ---- Phase A: raw scores, fp16 MMA with fp16 accumulator ----
    {
        wmma::fragment<wmma::matrix_a, 16, 16, 16, __half, wmma::row_major> a[4];
        #pragma unroll
        for (int kk = 0; kk < 4; kk++)
            wmma::load_matrix_sync(a[kk], sQ + kk * 16, 72);

        const __half* Kbase = gKh + (size_t)bh * SD_;
        uint2 pK[8];
        #pragma unroll
        for (int i = 0; i < 8; i++)
            pK[i] = *(const uint2*)(Kbase + (rowA + i * 16) * DK_ + c4);

        for (int nc = 0; nc < 8; nc++) {
            __syncthreads();
            #pragma unroll
            for (int i = 0; i < 8; i++)
                *(uint2*)&sKV[(rowA + i * 16) * 72 + c4] = pK[i];
            __syncthreads();
            if (nc < 7) {
                const int n1 = (nc + 1) * 128;
                #pragma unroll
                for (int i = 0; i < 8; i++)
                    pK[i] = *(const uint2*)(Kbase + (n1 + rowA + i * 16) * DK_ + c4);
            }
            const int ncol = wid * 16;
            wmma::fragment<wmma::accumulator, 16, 16, 16, __half> acc;
            wmma::fill_fragment(acc, __float2half(0.0f));
            #pragma unroll
            for (int kk = 0; kk < 4; kk++) {
                wmma::fragment<wmma::matrix_b, 16, 16, 16, __half, wmma::col_major> b;
                wmma::load_matrix_sync(b, sKV + ncol * 72 + kk * 16, 72);
                wmma::mma_sync(acc, a[kk], b, acc);
            }
            wmma::store_matrix_sync(sT + nc * 128 + ncol, acc, THP, wmma::mem_row_major);
        }
    }
    __syncthreads();

    // ---- Phase B: 3-pass softmax over fp16 scores + fp16 bias ----
    #pragma unroll
    for (int rr = 0; rr < 2; rr++) {
        int r = wid * 2 + rr;
        __half2* row2 = (__half2*)(sT + r * THP);
        __half2* gb = (__half2*)(gS + ((size_t)bh * S_ + q0 + r) * S_);
        float mx = -3.0e38f;
        #pragma unroll
        for (int jj = 0; jj < 16; jj++) {
            int p = lane + 32 * jj;
            float2 s = __half22float2(row2[p]);
            float2 bv = __half22float2(gb[p]);
            mx = fmaxf(mx, fmaxf(s.x + bv.x, s.y + bv.y));
        }
        #pragma unroll
        for (int o = 16; o; o >>= 1) mx = fmaxf(mx, __shfl_xor_sync(0xffffffffu, mx, o));
        float sum = 0.0f;
        #pragma unroll
        for (int jj = 0; jj < 16; jj++) {
            int p = lane + 32 * jj;
            float2 s = __half22float2(row2[p]);
            float2 bv = __half22float2(gb[p]);
            float e0 = expf(s.x + bv.x - mx);
            float e1 = expf(s.y + bv.y - mx);
            row2[p] = __floats2half2_rn(e0, e1);
            sum += e0 + e1;
        }
        #pragma unroll
        for (int o = 16; o; o >>= 1) sum += __shfl_xor_sync(0xffffffffu, sum, o);
        float inv = 1.0f / sum;
        #pragma unroll
        for (int jj = 0; jj < 16; jj++) {
            int p = lane + 32 * jj;
            float2 e = __half22float2(row2[p]);
            __half2 w = __floats2half2_rn(e.x * inv, e.y * inv);
            row2[p] = w;
            gb[p] = w;
        }
    }
    __syncthreads();

    // ---- Phase C: out = weights @ V; 128-k chunks, split-kk across warp halves ----
    {
        const int kg = wid >> 2;   // 0..1: kk 0-3 vs 4-7
        const int wc = wid & 3;    // 0..3 -> 16 cols
        wmma::fragment<wmma::accumulator, 16, 16, 16, float> c[2];
        wmma::fill_fragment(c[0], 0.0f);
        wmma::fill_fragment(c[1], 0.0f);
        const __half* Vbase = gVh + (size_t)bh * SD_;

        uint2 pV[8];
        #pragma unroll
        for (int i = 0; i < 8; i++)
            pV[i] = *(const uint2*)(Vbase + (rowA + i * 16) * DK_ + c4);

        for (int kt = 0; kt < 8; kt++) {
            __syncthreads();
            #pragma unroll
            for (int i = 0; i < 8; i++)
                *(uint2*)&sKV[(rowA + i * 16) * 72 + c4] = pV[i];
            __syncthreads();
            if (kt < 7) {
                const int k1 = (kt + 1) * 128;
                #pragma unroll
                for (int i = 0; i < 8; i++)
                    pV[i] = *(const uint2*)(Vbase + (k1 + rowA + i * 16) * DK_ + c4);
            }
            #pragma unroll
            for (int kx = 0; kx < 4; kx++) {
                const int kk = kg * 4 + kx;
                wmma::fragment<wmma::matrix_a, 16, 16, 16, __half, wmma::row_major> a;
                wmma::fragment<wmma::matrix_b, 16, 16, 16, __half, wmma::row_major> b;
                wmma::load_matrix_sync(a, sT + kt * 128 + kk * 16, THP);
                wmma::load_matrix_sync(b, sKV + (kk * 16) * 72 + wc * 16, 72);
                wmma::mma_sync(c[kx & 1], a, b, c[kx & 1]);
            }
        }
        #pragma unroll
        for (int e = 0; e < c[0].num_elements; e++) c[0].x[e] += c[1].x[e];

        // all warps must finish reading sT (weights) before recycling it
        __syncthreads();

        float* red = (float*)sT;   // weights dead; reuse as 16x68 fp32 stage
        if (kg == 1)
            wmma::store_matrix_sync(red + wc * 16, c[0], 68, wmma::mem_row_major);
        __syncthreads();
        if (kg == 0) {
            wmma::fragment<wmma::accumulator, 16, 16, 16, float> t;
            wmma::load_matrix_sync(t, red + wc * 16, 68, wmma::mem_row_major);
            #pragma unroll
            for (int e = 0; e < c[0].num_elements; e++) c[0].x[e] += t.x[e];
            wmma::store_matrix_sync(gO + (size_t)bh * SD_ + (size_t)q0 * DK_ + wc * 16,
                                    c[0], DK_, wmma::mem_row_major);
        }
    }
}

// ---------------------------------------------------------------------------
// Kernel 4: gO += weights[:,q,:] @ Ev[q].  fp16 MMA, fp16 weights from gS.
// ---------------------------------------------------------------------------
__global__ __launch_bounds__(256, 4)
void edgev_kernel(const float* __restrict__ Ev)
{
    __shared__ __half sA[64 * 72];
    __shared__ __half sB[64 * 72];

    const int tid = threadIdx.x;
    const int wid = tid >> 5;
    const int warpRow = wid >> 1;   // 0..3
    const int warpCol = wid & 1;    // 0..1
    const int q = blockIdx.x;
    const int rowA = tid >> 4;      // 0..15
    const int c4   = (tid & 15) * 4;

    wmma::fragment<wmma::accumulator, 16, 16, 16, float> acc[2];
    #pragma unroll
    for (int j = 0; j < 2; j++)
        wmma::load_matrix_sync(acc[j],
            gO + (size_t)(warpRow * 16) * SD_ + q * DK_ + warpCol * 32 + j * 16,
            SD_, wmma::mem_row_major);

    uint2  pA[4];
    float4 pB[4];
    #pragma unroll
    for (int i = 0; i < 4; i++) {
        int row = rowA + i * 16;
        pA[i] = *(const uint2*)(gS + (size_t)row * SS_ + (size_t)q * S_ + c4);
        pB[i] = *(const float4*)(Ev + ((size_t)q * S_ + row) * DK_ + c4);
    }

    for (int kt = 0; kt < 16; kt++) {
        __syncthreads();
        #pragma unroll
        for (int i = 0; i < 4; i++) {
            int row = rowA + i * 16;
            *(uint2*)&sA[row * 72 + c4] = pA[i];
            float4 v = pB[i];
            *(__half2*)&sB[row * 72 + c4]     = __floats2half2_rn(v.x, v.y);
            *(__half2*)&sB[row * 72 + c4 + 2] = __floats2half2_rn(v.z, v.w);
        }
        __syncthreads();
        if (kt < 15) {
            const int k1 = (kt + 1) * 64;
            #pragma unroll
            for (int i = 0; i < 4; i++) {
                int row = rowA + i * 16;
                pA[i] = *(const uint2*)(gS + (size_t)row * SS_ + (size_t)q * S_ + k1 + c4);
                pB[i] = *(const float4*)(Ev + ((size_t)q * S_ + k1 + row) * DK_ + c4);
            }
        }
        #pragma unroll
        for (int kk = 0; kk < 4; kk++) {
            wmma::fragment<wmma::matrix_a, 16, 16, 16, __half, wmma::row_major> a;
            wmma::load_matrix_sync(a, sA + (warpRow * 16) * 72 + kk * 16, 72);
            #pragma unroll
            for (int j = 0; j < 2; j++) {
                wmma::fragment<wmma::matrix_b, 16, 16, 16, __half, wmma::row_major> b;
                wmma::load_matrix_sync(b, sB + (kk * 16) * 72 + warpCol * 32 + j * 16, 72);
                wmma::mma_sync(acc[j], a, b, acc[j]);
            }
        }
    }

    #pragma unroll
    for (int j = 0; j < 2; j++)
        wmma::store_matrix_sync(
            gO + (size_t)(warpRow * 16) * SD_ + q * DK_ + warpCol * 32 + j * 16,
            acc[j], SD_, wmma::mem_row_major);
}

// ---------------------------------------------------------------------------
// Kernel 5: out = concat_heads(gO) @ Wp + bp. 3xbf16 split, tile 128x128.
// Halves gO re-reads vs the 128x64 tiling.
// ---------------------------------------------------------------------------
__global__ __launch_bounds__(256, 2)
void final_kernel(const float* __restrict__ Wp, const float* __restrict__ bp,
                  float* __restrict__ out)
{
    __shared__ float sBias[16 * 136];
    __shared__ __nv_bfloat16 sAhi[128 * 40], sAlo[128 * 40];
    __shared__ __nv_bfloat16 sBhi[32 * 136], sBlo[32 * 136];

    const int tid = threadIdx.x;
    const int wid = tid >> 5;
    const int warpRow = wid >> 1;   // 0..3 -> 32 rows
    const int warpCol = wid & 1;    // 0..1 -> 64 cols
    const int m0 = blockIdx.y * 128;
    const int n0 = blockIdx.x * 128;
    const int bb = m0 >> 10;
    const int sBase = m0 & 1023;

    #pragma unroll
    for (int i = 0; i < 8; i++) {
        int idx = tid + i * 256;
        int r = idx >> 7, c = idx & 127;
        sBias[r * 136 + c] = bp[n0 + c];
    }
    __syncthreads();

    wmma::fragment<wmma::accumulator, 16, 16, 16, float> acc[2][4];
    #pragma unroll
    for (int mi = 0; mi < 2; mi++)
        #pragma unroll
        for (int ni = 0; ni < 4; ni++)
            wmma::load_matrix_sync(acc[mi][ni], sBias + warpCol * 64 + ni * 16,
                                   136, wmma::mem_row_major);

    for (int kt = 0; kt < 16; kt++) {
        const int k0 = kt * 32;
        const int h = k0 >> 6, d0 = k0 & 63;
        const float* Abase = gO + ((size_t)((bb * H_ + h) << 16)) + d0;
        #pragma unroll
        for (int i = 0; i < 4; i++) {
            int fi = tid + i * 256;
            int row = fi >> 3, c4 = (fi & 7) * 4;
            float4 v = *(const float4*)(Abase + (size_t)(sBase + row) * DK_ + c4);
            __nv_bfloat16 hx = __float2bfloat16(v.x), hy = __float2bfloat16(v.y);
            __nv_bfloat16 hz = __float2bfloat16(v.z), hw = __float2bfloat16(v.w);
            *(__nv_bfloat162*)&sAhi[row * 40 + c4]     = __nv_bfloat162(hx, hy);
            *(__nv_bfloat162*)&sAhi[row * 40 + c4 + 2] = __nv_bfloat162(hz, hw);
            *(__nv_bfloat162*)&sAlo[row * 40 + c4] =
                __nv_bfloat162(__float2bfloat16(v.x - __bfloat162float(hx)),
                               __float2bfloat16(v.y - __bfloat162float(hy)));
            *(__nv_bfloat162*)&sAlo[row * 40 + c4 + 2] =
                __nv_bfloat162(__float2bfloat16(v.z - __bfloat162float(hz)),
                               __float2bfloat16(v.w - __bfloat162float(hw)));
        }
        #pragma unroll
        for (int i = 0; i < 4; i++) {
            int fi = tid + i * 256;
            int row = fi >> 5, c4 = (fi & 31) * 4;
            float4 v = *(const float4*)(Wp + (k0 + row) * HD_ + n0 + c4);
            __nv_bfloat16 hx = __float2bfloat16(v.x), hy = __float2bfloat16(v.y);
            __nv_bfloat16 hz = __float2bfloat16(v.z), hw = __float2bfloat16(v.w);
            *(__nv_bfloat162*)&sBhi[row * 136 + c4]     = __nv_bfloat162(hx, hy);
            *(__nv_bfloat162*)&sBhi[row * 136 + c4 + 2] = __nv_bfloat162(hz, hw);
            *(__nv_bfloat162*)&sBlo[row * 136 + c4] =
                __nv_bfloat162(__float2bfloat16(v.x - __bfloat162float(hx)),
                               __float2bfloat16(v.y - __bfloat162float(hy)));
            *(__nv_bfloat162*)&sBlo[row * 136 + c4 + 2] =
                __nv_bfloat162(__float2bfloat16(v.z - __bfloat162float(hz)),
                               __float2bfloat16(v.w - __bfloat162float(hw)));
        }
        __syncthreads();
        #pragma unroll
        for (int kk = 0; kk < 2; kk++) {
            #pragma unroll
            for (int mi = 0; mi < 2; mi++) {
                wmma::fragment<wmma::matrix_a, 16, 16, 16, __nv_bfloat16, wmma::row_major> ah, al;
                wmma::load_matrix_sync(ah, sAhi + (warpRow * 32 + mi * 16) * 40 + kk * 16, 40);
                wmma::load_matrix_sync(al, sAlo + (warpRow * 32 + mi * 16) * 40 + kk * 16, 40);
                #pragma unroll
                for (int ni = 0; ni < 4; ni++) {
                    wmma::fragment<wmma::matrix_b, 16, 16, 16, __nv_bfloat16, wmma::row_major> bh, bl;
                    wmma::load_matrix_sync(bh, sBhi + (kk * 16) * 136 + warpCol * 64 + ni * 16, 136);
                    wmma::load_matrix_sync(bl, sBlo + (kk * 16) * 136 + warpCol * 64 + ni * 16, 136);
                    wmma::mma_sync(acc[mi][ni], ah, bh, acc[mi][ni]);
                    wmma::mma_sync(acc[mi][ni], ah, bl, acc[mi][ni]);
                    wmma::mma_sync(acc[mi][ni], al, bh, acc[mi][ni]);
                }
            }
        }
        __syncthreads();
    }

    #pragma unroll
    for (int mi = 0; mi < 2; mi++)
        #pragma unroll
        for (int ni = 0; ni < 4; ni++)
            wmma::store_matrix_sync(
                out + (size_t)(m0 + warpRow * 32 + mi * 16) * HD_ + n0 + warpCol * 64 + ni * 16,
                acc[mi][ni], HD_, wmma::mem_row_major);
}

// ---------------------------------------------------------------------------
extern "C" void kernel_launch(void* const* d_in, const int* in_sizes, int n_in,
                              void* d_out, int out_size)
{
    const float* queries = (const float*)d_in[0];
    const float* keys    = (const float*)d_in[1];
    const float* values  = (const float*)d_in[2];
    const float* Ek      = (const float*)d_in[3];
    const float* Ev      = (const float*)d_in[4];
    const float* abias   = (const float*)d_in[5];
    const float* Wq = (const float*)d_in[6];
    const float* bq = (const float*)d_in[7];
    const float* Wk = (const float*)d_in[8];
    const float* bk = (const float*)d_in[9];
    const float* Wv = (const float*)d_in[10];
    const float* bv = (const float*)d_in[11];
    const float* Wp = (const float*)d_in[12];
    const float* bp = (const float*)d_in[13];
    float* out = (float*)d_out;

    const int SMEM_PR = 128 * 68 * 4;                                   // 34816
    const int SMEM_EB = 2 * 64 * 72 * 2 + 64 * 72 * 4;                  // 36864
    const int SMEM_FA = (16 * 72 + 128 * 72) * 2 + 16 * THP * 2;        // 53760
    cudaFuncSetAttribute(fused_attn_kernel, cudaFuncAttributeMaxDynamicSharedMemorySize, SMEM_FA);

    dim3 blk(256);
    proj_kernel<<<dim3(8, 64, 3), blk, SMEM_PR>>>(queries, keys, values, Wq, Wk, Wv, bq, bk, bv);
    edge_bias_kernel<<<dim3(16, 1024), blk, SMEM_EB>>>(Ek, abias);
    fused_attn_kernel<<<dim3(64, 64), blk, SMEM_FA>>>();
    edgev_kernel<<<1024, blk>>>(Ev);
    final_kernel<<<dim3(4, 64), blk>>>(Wp, bp, out);
}